// round 5
// baseline (speedup 1.0000x reference)
#include <cuda_runtime.h>
#include <cstdint>

#define NTHR 512
#define MT 128
#define BSZ 131072
#define NMAT 36
#define TOTAL_SLABS 288      // 36 mats x 8 slabs (K=32 each)
#define SLAB_FLOATS 8192
#define SLAB_BYTES 32768
#define ACT_STRIDE 136       // 136 mod 32 = 8 -> conflict-free B-frag column access

// smem byte offsets
#define OFF_WBUF 0                       // 2 x 32KB
#define OFF_ACT  65536                   // 256 x 136 x 4 = 139264
#define OFF_BIAS 204800
#define OFF_W1S  205824
#define OFF_B1S  206848
#define OFF_W5S  207872
#define OFF_XV   208896                  // 128 x 2 floats
#define OFF_PP   209920                  // 4 x 128 floats
#define OFF_SARR 211968
#define OFF_TARR 212480
#define SMEM_DYN 212992

__device__ float g_wpack[NMAT * 65536];

// ---------------------------------------------------------------------------
__device__ __forceinline__ uint32_t tf32r(float f) {
    uint32_t u; asm("cvt.rna.tf32.f32 %0, %1;" : "=r"(u) : "f"(f)); return u;
}
__device__ __forceinline__ void cpasync16(uint32_t dst, const void* src) {
    asm volatile("cp.async.cg.shared.global [%0], [%1], 16;" :: "r"(dst), "l"(src));
}
__device__ __forceinline__ void mma_tf32(float acc[4],
                                         uint32_t a0, uint32_t a1, uint32_t a2, uint32_t a3,
                                         uint32_t b0, uint32_t b1) {
    asm volatile(
        "mma.sync.aligned.m16n8k8.row.col.f32.tf32.tf32.f32 "
        "{%0,%1,%2,%3}, {%4,%5,%6,%7}, {%8,%9}, {%0,%1,%2,%3};"
        : "+f"(acc[0]), "+f"(acc[1]), "+f"(acc[2]), "+f"(acc[3])
        : "r"(a0), "r"(a1), "r"(a2), "r"(a3), "r"(b0), "r"(b1));
}

// ---------------------------------------------------------------------------
// prepack: W[k][n] -> tf32, A-fragment order for mma (A[m=n][k] = W[k][n]).
// frag id = ks*16 + mt (ks = kstep in slab, mt = n>>4); per frag 32 lanes x uint4.
// lane = (n&7)*4 + (k&3); slot = ((k>>2)&1)*2 + ((n>>3)&1)
// ---------------------------------------------------------------------------
__global__ void prepack_kernel(const float* sW2, const float* sW3, const float* sW4,
                               const float* tW2, const float* tW3, const float* tW4) {
    int gid = blockIdx.x * blockDim.x + threadIdx.x;
    if (gid >= NMAT * 65536) return;
    int mat = gid >> 16;
    int e   = gid & 65535;
    int k = e >> 8, n = e & 255;
    int st = mat / 18, rem = mat % 18, l = rem / 3, g = rem % 3;
    const float* src;
    switch (st * 3 + g) {
        case 0: src = sW2; break;
        case 1: src = sW3; break;
        case 2: src = sW4; break;
        case 3: src = tW2; break;
        case 4: src = tW3; break;
        default: src = tW4; break;
    }
    float v = src[l * 65536 + e];
    int slab = k >> 5, ks = (k >> 3) & 3, mt = n >> 4;
    int lane = (n & 7) * 4 + (k & 3);
    int slot = ((k >> 2) & 1) * 2 + ((n >> 3) & 1);
    int dst  = mat * 65536 + slab * SLAB_FLOATS + ((ks * 16 + mt) * 32 + lane) * 4 + slot;
    g_wpack[dst] = __uint_as_float(tf32r(v));
}

// ---------------------------------------------------------------------------
__global__ void __launch_bounds__(NTHR, 1)
realnvp_kernel(const float* __restrict__ X,
               const float* __restrict__ sW1, const float* __restrict__ sB1,
               const float* __restrict__ sB2, const float* __restrict__ sB3,
               const float* __restrict__ sB4, const float* __restrict__ sW5,
               const float* __restrict__ sB5,
               const float* __restrict__ tW1, const float* __restrict__ tB1,
               const float* __restrict__ tB2, const float* __restrict__ tB3,
               const float* __restrict__ tB4, const float* __restrict__ tW5,
               const float* __restrict__ tB5,
               float* __restrict__ out) {
    extern __shared__ char base[];
    float*    actf   = (float*)(base + OFF_ACT);
    uint32_t* actu   = (uint32_t*)actf;
    float*    bias_s = (float*)(base + OFF_BIAS);
    float*    w1s    = (float*)(base + OFF_W1S);
    float*    b1s    = (float*)(base + OFF_B1S);
    float*    w5s    = (float*)(base + OFF_W5S);
    float*    xv     = (float*)(base + OFF_XV);
    float*    pp     = (float*)(base + OFF_PP);     // [4][128]
    float*    sarr   = (float*)(base + OFF_SARR);
    float*    tarr   = (float*)(base + OFF_TARR);
    uint32_t  wbuf_sh = (uint32_t)__cvta_generic_to_shared(base + OFF_WBUF);

    int tid  = threadIdx.x;
    int wid  = tid >> 5, lane = tid & 31;
    int wm   = wid >> 2;          // 0..3 feature tiles of 64
    int wn   = wid & 3;           // 0..3 sample tiles of 32
    int u    = lane >> 2;         // 0..7
    int v    = lane & 3;          // 0..3
    int gbase = blockIdx.x * MT;

    float ldet = 0.f;
    if (tid < 128) {
        float2 xx = *(const float2*)&X[(gbase + tid) * 2];
        xv[tid * 2 + 0] = logf(xx.x / (1.f - xx.x));
        xv[tid * 2 + 1] = logf(xx.y / (1.f - xx.y));
    }

    // ---- weight slab prefetch (2-buffer ring) ----
    auto prefetch = [&](int q) {
        int qq = (q >= TOTAL_SLABS) ? q - TOTAL_SLABS : q;
        int j = qq >> 3, sl = qq & 7;
        int li = 5 - j / 6;
        int r6 = j % 6;
        int mat = ((r6 / 3) * 6 + li) * 3 + (r6 % 3);
        const float* src = g_wpack + (size_t)mat * 65536 + sl * SLAB_FLOATS + tid * 4;
        uint32_t dst = wbuf_sh + (uint32_t)(q & 1) * SLAB_BYTES + tid * 16;
#pragma unroll
        for (int it = 0; it < 4; it++)
            cpasync16(dst + it * 8192, src + it * 2048);
        asm volatile("cp.async.commit_group;");
    };

    prefetch(0);

    // ---- layer0: act[h][s] = relu(x[s]*W1[h] + B1[h]), tf32-rounded ----
    auto layer0 = [&](const float* w1row, const float* b1, int cdim) {
        if (tid < 256) { w1s[tid] = w1row[tid]; b1s[tid] = b1[tid]; }
        __syncthreads();
        int s4 = lane * 4;
        int kb = wid * 16;
        float x0 = xv[(s4 + 0) * 2 + cdim], x1 = xv[(s4 + 1) * 2 + cdim];
        float x2 = xv[(s4 + 2) * 2 + cdim], x3 = xv[(s4 + 3) * 2 + cdim];
#pragma unroll 4
        for (int i = 0; i < 16; i++) {
            int k = kb + i;
            float w = w1s[k], b = b1s[k];
            uint4 vv;
            vv.x = tf32r(fmaxf(fmaf(x0, w, b), 0.f));
            vv.y = tf32r(fmaxf(fmaf(x1, w, b), 0.f));
            vv.z = tf32r(fmaxf(fmaf(x2, w, b), 0.f));
            vv.w = tf32r(fmaxf(fmaf(x3, w, b), 0.f));
            *(uint4*)&actu[k * ACT_STRIDE + s4] = vv;
        }
        __syncthreads();
    };

    // ---- one 256x256 GEMM; epilogue either writes act or fuses the W5 dot ----
    auto gemm = [&](int gc, const float* bias, bool fuse,
                    const float* w5col, float b5, bool is_s) {
        if (tid < 256) {
            bias_s[tid] = bias[tid];
            if (fuse) w5s[tid] = w5col[tid * 2];
        }
        float acc[4][4][4];
#pragma unroll
        for (int a = 0; a < 4; a++)
#pragma unroll
            for (int b = 0; b < 4; b++)
#pragma unroll
                for (int q = 0; q < 4; q++) acc[a][b][q] = 0.f;

        const uint32_t* actu_b = actu + wn * 32 + u;

        for (int sl = 0; sl < 8; sl++) {
            int q = gc * 8 + sl;
            asm volatile("cp.async.wait_group 0;");
            __syncthreads();                 // buf q visible; buf (q+1)&1 free
            prefetch(q + 1);
            const float* wb = (const float*)(base + OFF_WBUF + (q & 1) * SLAB_BYTES);
#pragma unroll
            for (int ks = 0; ks < 4; ks++) {
                uint4 a[4];
#pragma unroll
                for (int mf = 0; mf < 4; mf++)
                    a[mf] = *(const uint4*)&wb[((ks * 16 + wm * 4 + mf) * 32 + lane) * 4];
                int kk = sl * 32 + ks * 8 + v;
                const uint32_t* p0 = actu_b + kk * ACT_STRIDE;
                const uint32_t* p1 = p0 + 4 * ACT_STRIDE;
                uint32_t b0[4], b1[4];
#pragma unroll
                for (int nf = 0; nf < 4; nf++) { b0[nf] = p0[nf * 8]; b1[nf] = p1[nf * 8]; }
#pragma unroll
                for (int mf = 0; mf < 4; mf++)
#pragma unroll
                    for (int nf = 0; nf < 4; nf++)
                        mma_tf32(acc[mf][nf], a[mf].x, a[mf].y, a[mf].z, a[mf].w,
                                 b0[nf], b1[nf]);
            }
        }
        __syncthreads();                     // all reads of act done before overwrite

        if (!fuse) {
            // bias + relu + tf32, vectorized STS.64, in-place into act
#pragma unroll
            for (int mf = 0; mf < 4; mf++) {
                int f0 = wm * 64 + mf * 16 + u;
                float bx = bias_s[f0], by = bias_s[f0 + 8];
#pragma unroll
                for (int nf = 0; nf < 4; nf++) {
                    int s0 = wn * 32 + nf * 8 + v * 2;
                    uint2 lo, hi;
                    lo.x = tf32r(fmaxf(acc[mf][nf][0] + bx, 0.f));
                    lo.y = tf32r(fmaxf(acc[mf][nf][1] + bx, 0.f));
                    hi.x = tf32r(fmaxf(acc[mf][nf][2] + by, 0.f));
                    hi.y = tf32r(fmaxf(acc[mf][nf][3] + by, 0.f));
                    *(uint2*)&actu[f0 * ACT_STRIDE + s0]       = lo;
                    *(uint2*)&actu[(f0 + 8) * ACT_STRIDE + s0] = hi;
                }
            }
            __syncthreads();
        } else {
            // fused H->1 dot: p[s] = sum_f relu(acc+bias) * w5[f]
            float p[4][2];
#pragma unroll
            for (int nf = 0; nf < 4; nf++) { p[nf][0] = 0.f; p[nf][1] = 0.f; }
#pragma unroll
            for (int mf = 0; mf < 4; mf++) {
                int f0 = wm * 64 + mf * 16 + u;
                float bx = bias_s[f0], by = bias_s[f0 + 8];
                float wa = w5s[f0],   wb5 = w5s[f0 + 8];
#pragma unroll
                for (int nf = 0; nf < 4; nf++) {
                    float v0 = fmaxf(acc[mf][nf][0] + bx, 0.f);
                    float v1 = fmaxf(acc[mf][nf][1] + bx, 0.f);
                    float v2 = fmaxf(acc[mf][nf][2] + by, 0.f);
                    float v3 = fmaxf(acc[mf][nf][3] + by, 0.f);
                    p[nf][0] = fmaf(v0, wa, fmaf(v2, wb5, p[nf][0]));
                    p[nf][1] = fmaf(v1, wa, fmaf(v3, wb5, p[nf][1]));
                }
            }
            // reduce over u (lane stride 4): 3 shfl rounds
#pragma unroll
            for (int nf = 0; nf < 4; nf++) {
#pragma unroll
                for (int j = 0; j < 2; j++) {
                    float t = p[nf][j];
                    t += __shfl_down_sync(0xffffffffu, t, 16);
                    t += __shfl_down_sync(0xffffffffu, t, 8);
                    t += __shfl_down_sync(0xffffffffu, t, 4);
                    if (lane < 4)
                        pp[wm * 128 + wn * 32 + nf * 8 + lane * 2 + j] = t;
                }
            }
            __syncthreads();
            if (tid < 128) {
                float o = pp[tid] + pp[128 + tid] + pp[256 + tid] + pp[384 + tid] + b5;
                if (is_s) sarr[tid] = tanhf(o);
                else      tarr[tid] = o;
            }
            __syncthreads();
        }
    };

    // ---- main flow: 6 coupling layers, reversed ----
    int gc = 0;
    for (int i = 5; i >= 0; i--) {
        int cdim = (i & 1) ? 0 : 1;
        int other = 1 - cdim;

        layer0(sW1 + i * 512 + cdim * 256, sB1 + i * 256, cdim);
        gemm(gc++, sB2 + i * 256, false, 0, 0.f, false);
        gemm(gc++, sB3 + i * 256, false, 0, 0.f, false);
        gemm(gc++, sB4 + i * 256, true, sW5 + i * 512 + other, sB5[i * 2 + other], true);

        layer0(tW1 + i * 512 + cdim * 256, tB1 + i * 256, cdim);
        gemm(gc++, tB2 + i * 256, false, 0, 0.f, false);
        gemm(gc++, tB3 + i * 256, false, 0, 0.f, false);
        gemm(gc++, tB4 + i * 256, true, tW5 + i * 512 + other, tB5[i * 2 + other], false);

        if (tid < 128) {
            float sv = sarr[tid], tv = tarr[tid];
            xv[tid * 2 + other] = (xv[tid * 2 + other] - tv) * expf(-sv);
            ldet -= sv;
        }
        __syncthreads();
    }

    if (tid < 128) {
        int g = gbase + tid;
        float2 o;
        o.x = 1.f / (1.f + expf(-xv[tid * 2 + 0]));
        o.y = 1.f / (1.f + expf(-xv[tid * 2 + 1]));
        *(float2*)&out[g * 2] = o;
        out[2 * BSZ + g] = ldet;
    }
    asm volatile("cp.async.wait_group 0;");
}

// ---------------------------------------------------------------------------
extern "C" void kernel_launch(void* const* d_in, const int* in_sizes, int n_in,
                              void* d_out, int out_size) {
    const float* X   = (const float*)d_in[0];
    const float* sW1 = (const float*)d_in[1];
    const float* sB1 = (const float*)d_in[2];
    const float* sW2 = (const float*)d_in[3];
    const float* sB2 = (const float*)d_in[4];
    const float* sW3 = (const float*)d_in[5];
    const float* sB3 = (const float*)d_in[6];
    const float* sW4 = (const float*)d_in[7];
    const float* sB4 = (const float*)d_in[8];
    const float* sW5 = (const float*)d_in[9];
    const float* sB5 = (const float*)d_in[10];
    const float* tW1 = (const float*)d_in[11];
    const float* tB1 = (const float*)d_in[12];
    const float* tW2 = (const float*)d_in[13];
    const float* tB2 = (const float*)d_in[14];
    const float* tW3 = (const float*)d_in[15];
    const float* tB3 = (const float*)d_in[16];
    const float* tW4 = (const float*)d_in[17];
    const float* tB4 = (const float*)d_in[18];
    const float* tW5 = (const float*)d_in[19];
    const float* tB5 = (const float*)d_in[20];

    cudaFuncSetAttribute(realnvp_kernel, cudaFuncAttributeMaxDynamicSharedMemorySize,
                         SMEM_DYN);

    prepack_kernel<<<(NMAT * 65536) / 256, 256>>>(sW2, sW3, sW4, tW2, tW3, tW4);
    realnvp_kernel<<<BSZ / MT, NTHR, SMEM_DYN>>>(
        X, sW1, sB1, sB2, sB3, sB4, sW5, sB5,
        tW1, tB1, tB2, tB3, tB4, tW5, tB5, (float*)d_out);
}

// round 6
// speedup vs baseline: 1.5314x; 1.5314x over previous
#include <cuda_runtime.h>
#include <cuda_fp16.h>
#include <cstdint>

#define NTHR 512
#define MT 128
#define BSZ 131072
#define NMAT 36
#define TOTAL_SLABS 288      // 36 mats x 8 slabs (K=32 each)
#define SLAB_HALVES 8192     // 32k x 256n fp16
#define SLAB_BYTES 16384
#define NBUF 3
#define STR2 136             // half2 words per act2 row; 136 mod 32 = 8 -> conflict-free

// smem byte offsets
#define OFF_WBUF 0                      // 3 x 16KB
#define OFF_ACT  49152                  // 128 rows x 136 words x 4B = 69632
#define OFF_BIAS 118784
#define OFF_W1S  119808
#define OFF_B1S  120832
#define OFF_W5S  121856
#define OFF_XV   122880                 // 128 x 2 floats
#define OFF_PP   123904                 // 4 x 128 floats
#define OFF_SARR 125952
#define OFF_TARR 126464
#define SMEM_DYN 126976

__device__ __half g_wpack[NMAT * 65536];

// ---------------------------------------------------------------------------
__device__ __forceinline__ void cpasync16(uint32_t dst, const void* src) {
    asm volatile("cp.async.cg.shared.global [%0], [%1], 16;" :: "r"(dst), "l"(src));
}
__device__ __forceinline__ void mma_f16(float acc[4], uint4 a, uint32_t b0, uint32_t b1) {
    asm volatile(
        "mma.sync.aligned.m16n8k16.row.col.f32.f16.f16.f32 "
        "{%0,%1,%2,%3}, {%4,%5,%6,%7}, {%8,%9}, {%0,%1,%2,%3};"
        : "+f"(acc[0]), "+f"(acc[1]), "+f"(acc[2]), "+f"(acc[3])
        : "r"(a.x), "r"(a.y), "r"(a.z), "r"(a.w), "r"(b0), "r"(b1));
}
__device__ __forceinline__ uint32_t h2u(float lo, float hi) {
    __half2 h = __floats2half2_rn(lo, hi);
    return *(uint32_t*)&h;
}

// ---------------------------------------------------------------------------
// prepack: W[k][n] fp32 -> fp16, A-fragment order for m16n8k16 with k-permutation
// kappa: slot 2j->feat j, 2j+1->j+8, 8+2j->j+4, 9+2j->j+12 (within 16-block).
// One thread builds one lane's uint4 (8 halves) -> fully coalesced stores.
// ---------------------------------------------------------------------------
__global__ void prepack_kernel(const float* sW2, const float* sW3, const float* sW4,
                               const float* tW2, const float* tW3, const float* tW4) {
    int idx = blockIdx.x * blockDim.x + threadIdx.x;
    if (idx >= NMAT * 8192) return;     // one uint4 (8 halves) per thread
    int lane = idx & 31;
    int mt   = (idx >> 5) & 15;
    int kc   = (idx >> 9) & 1;
    int slab = (idx >> 10) & 7;
    int mat  = idx >> 13;

    int st = mat / 18, rem = mat % 18, l = rem / 3, g = rem % 3;
    const float* src;
    switch (st * 3 + g) {
        case 0: src = sW2; break;
        case 1: src = sW3; break;
        case 2: src = sW4; break;
        case 3: src = tW2; break;
        case 4: src = tW3; break;
        default: src = tW4; break;
    }
    src += l * 65536;

    int v = lane & 3, mlow = lane >> 2;
    int kb = slab * 32 + kc * 16;       // k base of this 16-chunk
    int nb = mt * 16;                   // feature (A row) base

    // reg0/1: slots 2v,2v+1 -> features v, v+8 ; reg2/3: slots 8+2v,9+2v -> v+4, v+12
    uint4 o;
    o.x = h2u(src[(kb + v)     * 256 + nb + mlow],     src[(kb + v + 8)  * 256 + nb + mlow]);
    o.y = h2u(src[(kb + v)     * 256 + nb + mlow + 8], src[(kb + v + 8)  * 256 + nb + mlow + 8]);
    o.z = h2u(src[(kb + v + 4) * 256 + nb + mlow],     src[(kb + v + 12) * 256 + nb + mlow]);
    o.w = h2u(src[(kb + v + 4) * 256 + nb + mlow + 8], src[(kb + v + 12) * 256 + nb + mlow + 8]);

    *(uint4*)(g_wpack + (size_t)mat * 65536 + slab * SLAB_HALVES
              + ((kc * 16 + mt) * 32 + lane) * 8) = o;
}

// ---------------------------------------------------------------------------
__global__ void __launch_bounds__(NTHR, 1)
realnvp_kernel(const float* __restrict__ X,
               const float* __restrict__ sW1, const float* __restrict__ sB1,
               const float* __restrict__ sB2, const float* __restrict__ sB3,
               const float* __restrict__ sB4, const float* __restrict__ sW5,
               const float* __restrict__ sB5,
               const float* __restrict__ tW1, const float* __restrict__ tB1,
               const float* __restrict__ tB2, const float* __restrict__ tB3,
               const float* __restrict__ tB4, const float* __restrict__ tW5,
               const float* __restrict__ tB5,
               float* __restrict__ out) {
    extern __shared__ char base[];
    uint32_t* actu   = (uint32_t*)(base + OFF_ACT);   // half2 words [row][STR2]
    float*    bias_s = (float*)(base + OFF_BIAS);
    float*    w1s    = (float*)(base + OFF_W1S);
    float*    b1s    = (float*)(base + OFF_B1S);
    float*    w5s    = (float*)(base + OFF_W5S);
    float*    xv     = (float*)(base + OFF_XV);
    float*    pp     = (float*)(base + OFF_PP);       // [4][128]
    float*    sarr   = (float*)(base + OFF_SARR);
    float*    tarr   = (float*)(base + OFF_TARR);
    uint32_t  wbuf_sh = (uint32_t)__cvta_generic_to_shared(base + OFF_WBUF);

    int tid  = threadIdx.x;
    int wid  = tid >> 5, lane = tid & 31;
    int wm   = wid >> 2;          // 0..3 feature tiles of 64
    int wn   = wid & 3;           // 0..3 sample tiles of 32
    int u    = lane >> 2;         // 0..7
    int v    = lane & 3;          // 0..3
    int gbase = blockIdx.x * MT;

    float ldet = 0.f;
    if (tid < 128) {
        float2 xx = *(const float2*)&X[(gbase + tid) * 2];
        xv[tid * 2 + 0] = logf(xx.x / (1.f - xx.x));
        xv[tid * 2 + 1] = logf(xx.y / (1.f - xx.y));
    }

    // ---- weight slab prefetch (3-buffer ring of 16KB) ----
    auto prefetch = [&](int q) {
        int qq = (q >= TOTAL_SLABS) ? q - TOTAL_SLABS : q;
        int j = qq >> 3, sl = qq & 7;
        int li = 5 - j / 6;
        int r6 = j % 6;
        int mat = ((r6 / 3) * 6 + li) * 3 + (r6 % 3);
        const __half* src = g_wpack + (size_t)mat * 65536 + sl * SLAB_HALVES + tid * 8;
        uint32_t dst = wbuf_sh + (uint32_t)(q % NBUF) * SLAB_BYTES + tid * 16;
        cpasync16(dst, src);
        cpasync16(dst + 8192, src + 4096);
        asm volatile("cp.async.commit_group;");
    };

    prefetch(0);
    prefetch(1);

    // ---- layer0: act row r holds features (16t+j, 16t+j+8), t=r>>3, j=r&7 ----
    auto layer0 = [&](const float* w1row, const float* b1, int cdim) {
        if (tid < 256) { w1s[tid] = w1row[tid]; b1s[tid] = b1[tid]; }
        __syncthreads();
        int r = tid >> 2;
        int k0 = ((r >> 3) << 4) + (r & 7), k1 = k0 + 8;
        float w0 = w1s[k0], bb0 = b1s[k0];
        float w1v = w1s[k1], bb1 = b1s[k1];
        int sbase = (tid & 3) * 32;
#pragma unroll 2
        for (int i = 0; i < 8; i++) {
            uint4 wrds;
            int s = sbase + i * 4;
            float x0 = xv[(s + 0) * 2 + cdim], x1 = xv[(s + 1) * 2 + cdim];
            float x2 = xv[(s + 2) * 2 + cdim], x3 = xv[(s + 3) * 2 + cdim];
            wrds.x = h2u(fmaxf(fmaf(x0, w0, bb0), 0.f), fmaxf(fmaf(x0, w1v, bb1), 0.f));
            wrds.y = h2u(fmaxf(fmaf(x1, w0, bb0), 0.f), fmaxf(fmaf(x1, w1v, bb1), 0.f));
            wrds.z = h2u(fmaxf(fmaf(x2, w0, bb0), 0.f), fmaxf(fmaf(x2, w1v, bb1), 0.f));
            wrds.w = h2u(fmaxf(fmaf(x3, w0, bb0), 0.f), fmaxf(fmaf(x3, w1v, bb1), 0.f));
            *(uint4*)&actu[r * STR2 + s] = wrds;
        }
        __syncthreads();
    };

    // ---- one 256x256 GEMM; epilogue writes act (half2 pairs) or fuses W5 dot ----
    auto gemm = [&](int gc, const float* bias, bool fuse,
                    const float* w5col, float b5, bool is_s) {
        if (tid < 256) {
            bias_s[tid] = bias[tid];
            if (fuse) w5s[tid] = w5col[tid * 2];
        }
        float acc[4][4][4];
#pragma unroll
        for (int a = 0; a < 4; a++)
#pragma unroll
            for (int b = 0; b < 4; b++)
#pragma unroll
                for (int q = 0; q < 4; q++) acc[a][b][q] = 0.f;

        for (int sl = 0; sl < 8; sl++) {
            int q = gc * 8 + sl;
            asm volatile("cp.async.wait_group 1;");
            __syncthreads();             // slab q visible; buf (q+2)%3 free
            prefetch(q + 2);
            const __half* wb = (const __half*)(base + OFF_WBUF + (q % NBUF) * SLAB_BYTES);
#pragma unroll
            for (int kc = 0; kc < 2; kc++) {
                uint4 a[4];
#pragma unroll
                for (int mf = 0; mf < 4; mf++)
                    a[mf] = *(const uint4*)(wb + ((kc * 16 + wm * 4 + mf) * 32 + lane) * 8);
                int kg = sl * 2 + kc;
                const uint32_t* p0 = actu + (kg * 8 + v) * STR2 + wn * 32 + u;
                uint32_t b0[4], b1[4];
#pragma unroll
                for (int nf = 0; nf < 4; nf++) {
                    b0[nf] = p0[nf * 8];
                    b1[nf] = p0[4 * STR2 + nf * 8];
                }
#pragma unroll
                for (int mf = 0; mf < 4; mf++)
#pragma unroll
                    for (int nf = 0; nf < 4; nf++)
                        mma_f16(acc[mf][nf], a[mf], b0[nf], b1[nf]);
            }
        }
        __syncthreads();                 // all reads of act done before overwrite

        if (!fuse) {
            // bias + relu + fp16 pair store: row = 8*(wm*4+mf) + u holds (f0, f0+8)
#pragma unroll
            for (int mf = 0; mf < 4; mf++) {
                int f0 = wm * 64 + mf * 16 + u;
                int row = (wm * 4 + mf) * 8 + u;
                float bx = bias_s[f0], by = bias_s[f0 + 8];
#pragma unroll
                for (int nf = 0; nf < 4; nf++) {
                    int s0 = wn * 32 + nf * 8 + v * 2;
                    uint2 wr;
                    wr.x = h2u(fmaxf(acc[mf][nf][0] + bx, 0.f),
                               fmaxf(acc[mf][nf][2] + by, 0.f));
                    wr.y = h2u(fmaxf(acc[mf][nf][1] + bx, 0.f),
                               fmaxf(acc[mf][nf][3] + by, 0.f));
                    *(uint2*)&actu[row * STR2 + s0] = wr;
                }
            }
            __syncthreads();
        } else {
            // fused H->1 dot: p[s] = sum_f relu(acc+bias) * w5[f]
            float p[4][2];
#pragma unroll
            for (int nf = 0; nf < 4; nf++) { p[nf][0] = 0.f; p[nf][1] = 0.f; }
#pragma unroll
            for (int mf = 0; mf < 4; mf++) {
                int f0 = wm * 64 + mf * 16 + u;
                float bx = bias_s[f0], by = bias_s[f0 + 8];
                float wa = w5s[f0],   wb5 = w5s[f0 + 8];
#pragma unroll
                for (int nf = 0; nf < 4; nf++) {
                    float v0 = fmaxf(acc[mf][nf][0] + bx, 0.f);
                    float v1 = fmaxf(acc[mf][nf][1] + bx, 0.f);
                    float v2 = fmaxf(acc[mf][nf][2] + by, 0.f);
                    float v3 = fmaxf(acc[mf][nf][3] + by, 0.f);
                    p[nf][0] = fmaf(v0, wa, fmaf(v2, wb5, p[nf][0]));
                    p[nf][1] = fmaf(v1, wa, fmaf(v3, wb5, p[nf][1]));
                }
            }
#pragma unroll
            for (int nf = 0; nf < 4; nf++) {
#pragma unroll
                for (int j = 0; j < 2; j++) {
                    float t = p[nf][j];
                    t += __shfl_down_sync(0xffffffffu, t, 16);
                    t += __shfl_down_sync(0xffffffffu, t, 8);
                    t += __shfl_down_sync(0xffffffffu, t, 4);
                    if (lane < 4)
                        pp[wm * 128 + wn * 32 + nf * 8 + lane * 2 + j] = t;
                }
            }
            __syncthreads();
            if (tid < 128) {
                float o = pp[tid] + pp[128 + tid] + pp[256 + tid] + pp[384 + tid] + b5;
                if (is_s) sarr[tid] = tanhf(o);
                else      tarr[tid] = o;
            }
            __syncthreads();
        }
    };

    // ---- main flow: 6 coupling layers, reversed ----
    int gc = 0;
    for (int i = 5; i >= 0; i--) {
        int cdim = (i & 1) ? 0 : 1;
        int other = 1 - cdim;

        layer0(sW1 + i * 512 + cdim * 256, sB1 + i * 256, cdim);
        gemm(gc++, sB2 + i * 256, false, 0, 0.f, false);
        gemm(gc++, sB3 + i * 256, false, 0, 0.f, false);
        gemm(gc++, sB4 + i * 256, true, sW5 + i * 512 + other, sB5[i * 2 + other], true);

        layer0(tW1 + i * 512 + cdim * 256, tB1 + i * 256, cdim);
        gemm(gc++, tB2 + i * 256, false, 0, 0.f, false);
        gemm(gc++, tB3 + i * 256, false, 0, 0.f, false);
        gemm(gc++, tB4 + i * 256, true, tW5 + i * 512 + other, tB5[i * 2 + other], false);

        if (tid < 128) {
            float sv = sarr[tid], tv = tarr[tid];
            xv[tid * 2 + other] = (xv[tid * 2 + other] - tv) * expf(-sv);
            ldet -= sv;
        }
        __syncthreads();
    }

    if (tid < 128) {
        int g = gbase + tid;
        float2 o;
        o.x = 1.f / (1.f + expf(-xv[tid * 2 + 0]));
        o.y = 1.f / (1.f + expf(-xv[tid * 2 + 1]));
        *(float2*)&out[g * 2] = o;
        out[2 * BSZ + g] = ldet;
    }
    asm volatile("cp.async.wait_group 0;");
}

// ---------------------------------------------------------------------------
extern "C" void kernel_launch(void* const* d_in, const int* in_sizes, int n_in,
                              void* d_out, int out_size) {
    const float* X   = (const float*)d_in[0];
    const float* sW1 = (const float*)d_in[1];
    const float* sB1 = (const float*)d_in[2];
    const float* sW2 = (const float*)d_in[3];
    const float* sB2 = (const float*)d_in[4];
    const float* sW3 = (const float*)d_in[5];
    const float* sB3 = (const float*)d_in[6];
    const float* sW4 = (const float*)d_in[7];
    const float* sB4 = (const float*)d_in[8];
    const float* sW5 = (const float*)d_in[9];
    const float* sB5 = (const float*)d_in[10];
    const float* tW1 = (const float*)d_in[11];
    const float* tB1 = (const float*)d_in[12];
    const float* tW2 = (const float*)d_in[13];
    const float* tB2 = (const float*)d_in[14];
    const float* tW3 = (const float*)d_in[15];
    const float* tB3 = (const float*)d_in[16];
    const float* tW4 = (const float*)d_in[17];
    const float* tB4 = (const float*)d_in[18];
    const float* tW5 = (const float*)d_in[19];
    const float* tB5 = (const float*)d_in[20];

    cudaFuncSetAttribute(realnvp_kernel, cudaFuncAttributeMaxDynamicSharedMemorySize,
                         SMEM_DYN);

    prepack_kernel<<<(NMAT * 8192 + 255) / 256, 256>>>(sW2, sW3, sW4, tW2, tW3, tW4);
    realnvp_kernel<<<BSZ / MT, NTHR, SMEM_DYN>>>(
        X, sW1, sB1, sB2, sB3, sB4, sW5, sB5,
        tW1, tB1, tB2, tB3, tB4, tW5, tB5, (float*)d_out);
}

// round 7
// speedup vs baseline: 1.9153x; 1.2507x over previous
#include <cuda_runtime.h>
#include <cuda_fp16.h>
#include <cstdint>

#define NTHR 512
#define MT 128
#define BSZ 131072
#define NMAT 36
#define TOTAL_SLABS 72       // 36 mats x 2 slabs (K=128 each)
#define SLAB_HALVES 32768    // 128k x 256n fp16
#define SLAB_BYTES 65536
#define STR2 136             // half2 words per act2 row; 136 mod 32 = 8 -> conflict-free

// smem byte offsets
#define OFF_WBUF 0                      // 2 x 64KB
#define OFF_ACT  131072                 // 128 rows x 136 words x 4B = 69632
#define OFF_BIAS 200704
#define OFF_W1S  201728
#define OFF_B1S  202752
#define OFF_W5S  203776
#define OFF_XV   204800                 // 128 x 2 floats
#define OFF_PP   205824                 // 4 x 128 floats
#define OFF_SARR 207872
#define OFF_TARR 208384
#define SMEM_DYN 208896

__device__ __half g_wpack[NMAT * 65536];

// ---------------------------------------------------------------------------
__device__ __forceinline__ void cpasync16(uint32_t dst, const void* src) {
    asm volatile("cp.async.cg.shared.global [%0], [%1], 16;" :: "r"(dst), "l"(src));
}
__device__ __forceinline__ void mma_f16(float acc[4], uint4 a, uint32_t b0, uint32_t b1) {
    asm volatile(
        "mma.sync.aligned.m16n8k16.row.col.f32.f16.f16.f32 "
        "{%0,%1,%2,%3}, {%4,%5,%6,%7}, {%8,%9}, {%0,%1,%2,%3};"
        : "+f"(acc[0]), "+f"(acc[1]), "+f"(acc[2]), "+f"(acc[3])
        : "r"(a.x), "r"(a.y), "r"(a.z), "r"(a.w), "r"(b0), "r"(b1));
}
__device__ __forceinline__ uint32_t h2u(float lo, float hi) {
    __half2 h = __floats2half2_rn(lo, hi);
    return *(uint32_t*)&h;
}

// ---------------------------------------------------------------------------
// prepack: W[k][n] fp32 -> fp16, A-fragment order for m16n8k16 with k-permutation
// kappa: slot 2j->feat j, 2j+1->j+8, 8+2j->j+4, 9+2j->j+12 (within 16-block).
// One thread builds one lane's uint4 (8 halves) -> fully coalesced stores.
// Slab = K=128 (32768 halves).
// ---------------------------------------------------------------------------
__global__ void prepack_kernel(const float* sW2, const float* sW3, const float* sW4,
                               const float* tW2, const float* tW3, const float* tW4) {
    int idx = blockIdx.x * blockDim.x + threadIdx.x;
    if (idx >= NMAT * 8192) return;     // one uint4 (8 halves) per thread
    int lane = idx & 31;
    int mt   = (idx >> 5) & 15;
    int kc   = (idx >> 9) & 7;
    int slab = (idx >> 12) & 1;
    int mat  = idx >> 13;

    int st = mat / 18, rem = mat % 18, l = rem / 3, g = rem % 3;
    const float* src;
    switch (st * 3 + g) {
        case 0: src = sW2; break;
        case 1: src = sW3; break;
        case 2: src = sW4; break;
        case 3: src = tW2; break;
        case 4: src = tW3; break;
        default: src = tW4; break;
    }
    src += l * 65536;

    int v = lane & 3, mlow = lane >> 2;
    int kb = slab * 128 + kc * 16;      // k base of this 16-chunk
    int nb = mt * 16;                   // feature (A row) base

    // reg0/1: slots 2v,2v+1 -> features v, v+8 ; reg2/3: slots 8+2v,9+2v -> v+4, v+12
    uint4 o;
    o.x = h2u(src[(kb + v)     * 256 + nb + mlow],     src[(kb + v + 8)  * 256 + nb + mlow]);
    o.y = h2u(src[(kb + v)     * 256 + nb + mlow + 8], src[(kb + v + 8)  * 256 + nb + mlow + 8]);
    o.z = h2u(src[(kb + v + 4) * 256 + nb + mlow],     src[(kb + v + 12) * 256 + nb + mlow]);
    o.w = h2u(src[(kb + v + 4) * 256 + nb + mlow + 8], src[(kb + v + 12) * 256 + nb + mlow + 8]);

    *(uint4*)(g_wpack + (size_t)mat * 65536 + slab * SLAB_HALVES
              + ((kc * 16 + mt) * 32 + lane) * 8) = o;
}

// ---------------------------------------------------------------------------
__global__ void __launch_bounds__(NTHR, 1)
realnvp_kernel(const float* __restrict__ X,
               const float* __restrict__ sW1, const float* __restrict__ sB1,
               const float* __restrict__ sB2, const float* __restrict__ sB3,
               const float* __restrict__ sB4, const float* __restrict__ sW5,
               const float* __restrict__ sB5,
               const float* __restrict__ tW1, const float* __restrict__ tB1,
               const float* __restrict__ tB2, const float* __restrict__ tB3,
               const float* __restrict__ tB4, const float* __restrict__ tW5,
               const float* __restrict__ tB5,
               float* __restrict__ out) {
    extern __shared__ char base[];
    uint32_t* actu   = (uint32_t*)(base + OFF_ACT);   // half2 words [row][STR2]
    float*    bias_s = (float*)(base + OFF_BIAS);
    float*    w1s    = (float*)(base + OFF_W1S);
    float*    b1s    = (float*)(base + OFF_B1S);
    float*    w5s    = (float*)(base + OFF_W5S);
    float*    xv     = (float*)(base + OFF_XV);
    float*    pp     = (float*)(base + OFF_PP);       // [4][128]
    float*    sarr   = (float*)(base + OFF_SARR);
    float*    tarr   = (float*)(base + OFF_TARR);
    uint32_t  wbuf_sh = (uint32_t)__cvta_generic_to_shared(base + OFF_WBUF);

    int tid  = threadIdx.x;
    int wid  = tid >> 5, lane = tid & 31;
    int wm   = wid >> 2;          // 0..3 feature tiles of 64
    int wn   = wid & 3;           // 0..3 sample tiles of 32
    int u    = lane >> 2;         // 0..7
    int v    = lane & 3;          // 0..3
    int gbase = blockIdx.x * MT;

    float ldet = 0.f;
    if (tid < 128) {
        float2 xx = *(const float2*)&X[(gbase + tid) * 2];
        xv[tid * 2 + 0] = logf(xx.x / (1.f - xx.x));
        xv[tid * 2 + 1] = logf(xx.y / (1.f - xx.y));
    }

    // ---- weight slab prefetch (2-buffer ring of 64KB) ----
    auto prefetch = [&](int q) {
        int qq = (q >= TOTAL_SLABS) ? q - TOTAL_SLABS : q;
        int j = qq >> 1, sl = qq & 1;
        int li = 5 - j / 6;
        int r6 = j % 6;
        int mat = ((r6 / 3) * 6 + li) * 3 + (r6 % 3);
        const __half* src = g_wpack + (size_t)mat * 65536 + sl * SLAB_HALVES + tid * 8;
        uint32_t dst = wbuf_sh + (uint32_t)(q & 1) * SLAB_BYTES + tid * 16;
#pragma unroll
        for (int it = 0; it < 8; it++)
            cpasync16(dst + it * 8192, src + it * 4096);
        asm volatile("cp.async.commit_group;");
    };

    prefetch(0);

    // ---- layer0: act row r holds features (16t+j, 16t+j+8), t=r>>3, j=r&7 ----
    auto layer0 = [&](const float* w1row, const float* b1, int cdim) {
        if (tid < 256) { w1s[tid] = w1row[tid]; b1s[tid] = b1[tid]; }
        __syncthreads();
        int r = tid >> 2;
        int k0 = ((r >> 3) << 4) + (r & 7), k1 = k0 + 8;
        float w0 = w1s[k0], bb0 = b1s[k0];
        float w1v = w1s[k1], bb1 = b1s[k1];
        int sbase = (tid & 3) * 32;
#pragma unroll 2
        for (int i = 0; i < 8; i++) {
            uint4 wrds;
            int s = sbase + i * 4;
            float x0 = xv[(s + 0) * 2 + cdim], x1 = xv[(s + 1) * 2 + cdim];
            float x2 = xv[(s + 2) * 2 + cdim], x3 = xv[(s + 3) * 2 + cdim];
            wrds.x = h2u(fmaxf(fmaf(x0, w0, bb0), 0.f), fmaxf(fmaf(x0, w1v, bb1), 0.f));
            wrds.y = h2u(fmaxf(fmaf(x1, w0, bb0), 0.f), fmaxf(fmaf(x1, w1v, bb1), 0.f));
            wrds.z = h2u(fmaxf(fmaf(x2, w0, bb0), 0.f), fmaxf(fmaf(x2, w1v, bb1), 0.f));
            wrds.w = h2u(fmaxf(fmaf(x3, w0, bb0), 0.f), fmaxf(fmaf(x3, w1v, bb1), 0.f));
            *(uint4*)&actu[r * STR2 + s] = wrds;
        }
        __syncthreads();
    };

    // ---- one 256x256 GEMM (2 K=128 slabs); epilogue writes act or fuses W5 dot ----
    auto gemm = [&](int gc, const float* bias, bool fuse,
                    const float* w5col, float b5, bool is_s) {
        if (tid < 256) {
            bias_s[tid] = bias[tid];
            if (fuse) w5s[tid] = w5col[tid * 2];
        }
        float acc[4][4][4];
#pragma unroll
        for (int a = 0; a < 4; a++)
#pragma unroll
            for (int b = 0; b < 4; b++)
#pragma unroll
                for (int q = 0; q < 4; q++) acc[a][b][q] = 0.f;

#pragma unroll 1
        for (int sl = 0; sl < 2; sl++) {
            int q = gc * 2 + sl;
            asm volatile("cp.async.wait_group 0;");
            __syncthreads();             // slab q visible; buf (q+1)&1 free
            prefetch(q + 1);
            const __half* wb = (const __half*)(base + OFF_WBUF + (q & 1) * SLAB_BYTES);
#pragma unroll
            for (int kc = 0; kc < 8; kc++) {
                uint4 a[4];
#pragma unroll
                for (int mf = 0; mf < 4; mf++)
                    a[mf] = *(const uint4*)(wb + ((kc * 16 + wm * 4 + mf) * 32 + lane) * 8);
                int kg = sl * 8 + kc;
                const uint32_t* p0 = actu + (kg * 8 + v) * STR2 + wn * 32 + u;
                uint32_t b0[4], b1[4];
#pragma unroll
                for (int nf = 0; nf < 4; nf++) {
                    b0[nf] = p0[nf * 8];
                    b1[nf] = p0[4 * STR2 + nf * 8];
                }
#pragma unroll
                for (int mf = 0; mf < 4; mf++)
#pragma unroll
                    for (int nf = 0; nf < 4; nf++)
                        mma_f16(acc[mf][nf], a[mf], b0[nf], b1[nf]);
            }
        }
        __syncthreads();                 // all reads of act done before overwrite

        if (!fuse) {
            // bias + relu + fp16 pair store: row = 8*(wm*4+mf) + u holds (f0, f0+8)
#pragma unroll
            for (int mf = 0; mf < 4; mf++) {
                int f0 = wm * 64 + mf * 16 + u;
                int row = (wm * 4 + mf) * 8 + u;
                float bx = bias_s[f0], by = bias_s[f0 + 8];
#pragma unroll
                for (int nf = 0; nf < 4; nf++) {
                    int s0 = wn * 32 + nf * 8 + v * 2;
                    uint2 wr;
                    wr.x = h2u(fmaxf(acc[mf][nf][0] + bx, 0.f),
                               fmaxf(acc[mf][nf][2] + by, 0.f));
                    wr.y = h2u(fmaxf(acc[mf][nf][1] + bx, 0.f),
                               fmaxf(acc[mf][nf][3] + by, 0.f));
                    *(uint2*)&actu[row * STR2 + s0] = wr;
                }
            }
            __syncthreads();
        } else {
            // fused H->1 dot: p[s] = sum_f relu(acc+bias) * w5[f]
            float p[4][2];
#pragma unroll
            for (int nf = 0; nf < 4; nf++) { p[nf][0] = 0.f; p[nf][1] = 0.f; }
#pragma unroll
            for (int mf = 0; mf < 4; mf++) {
                int f0 = wm * 64 + mf * 16 + u;
                float bx = bias_s[f0], by = bias_s[f0 + 8];
                float wa = w5s[f0],   wb5 = w5s[f0 + 8];
#pragma unroll
                for (int nf = 0; nf < 4; nf++) {
                    float v0 = fmaxf(acc[mf][nf][0] + bx, 0.f);
                    float v1 = fmaxf(acc[mf][nf][1] + bx, 0.f);
                    float v2 = fmaxf(acc[mf][nf][2] + by, 0.f);
                    float v3 = fmaxf(acc[mf][nf][3] + by, 0.f);
                    p[nf][0] = fmaf(v0, wa, fmaf(v2, wb5, p[nf][0]));
                    p[nf][1] = fmaf(v1, wa, fmaf(v3, wb5, p[nf][1]));
                }
            }
#pragma unroll
            for (int nf = 0; nf < 4; nf++) {
#pragma unroll
                for (int j = 0; j < 2; j++) {
                    float t = p[nf][j];
                    t += __shfl_down_sync(0xffffffffu, t, 16);
                    t += __shfl_down_sync(0xffffffffu, t, 8);
                    t += __shfl_down_sync(0xffffffffu, t, 4);
                    if (lane < 4)
                        pp[wm * 128 + wn * 32 + nf * 8 + lane * 2 + j] = t;
                }
            }
            __syncthreads();
            if (tid < 128) {
                float o = pp[tid] + pp[128 + tid] + pp[256 + tid] + pp[384 + tid] + b5;
                if (is_s) sarr[tid] = tanhf(o);
                else      tarr[tid] = o;
            }
            __syncthreads();
        }
    };

    // ---- main flow: 6 coupling layers, reversed ----
    int gc = 0;
    for (int i = 5; i >= 0; i--) {
        int cdim = (i & 1) ? 0 : 1;
        int other = 1 - cdim;

        layer0(sW1 + i * 512 + cdim * 256, sB1 + i * 256, cdim);
        gemm(gc++, sB2 + i * 256, false, 0, 0.f, false);
        gemm(gc++, sB3 + i * 256, false, 0, 0.f, false);
        gemm(gc++, sB4 + i * 256, true, sW5 + i * 512 + other, sB5[i * 2 + other], true);

        layer0(tW1 + i * 512 + cdim * 256, tB1 + i * 256, cdim);
        gemm(gc++, tB2 + i * 256, false, 0, 0.f, false);
        gemm(gc++, tB3 + i * 256, false, 0, 0.f, false);
        gemm(gc++, tB4 + i * 256, true, tW5 + i * 512 + other, tB5[i * 2 + other], false);

        if (tid < 128) {
            float sv = sarr[tid], tv = tarr[tid];
            xv[tid * 2 + other] = (xv[tid * 2 + other] - tv) * expf(-sv);
            ldet -= sv;
        }
        __syncthreads();
    }

    if (tid < 128) {
        int g = gbase + tid;
        float2 o;
        o.x = 1.f / (1.f + expf(-xv[tid * 2 + 0]));
        o.y = 1.f / (1.f + expf(-xv[tid * 2 + 1]));
        *(float2*)&out[g * 2] = o;
        out[2 * BSZ + g] = ldet;
    }
    asm volatile("cp.async.wait_group 0;");
}

// ---------------------------------------------------------------------------
extern "C" void kernel_launch(void* const* d_in, const int* in_sizes, int n_in,
                              void* d_out, int out_size) {
    const float* X   = (const float*)d_in[0];
    const float* sW1 = (const float*)d_in[1];
    const float* sB1 = (const float*)d_in[2];
    const float* sW2 = (const float*)d_in[3];
    const float* sB2 = (const float*)d_in[4];
    const float* sW3 = (const float*)d_in[5];
    const float* sB3 = (const float*)d_in[6];
    const float* sW4 = (const float*)d_in[7];
    const float* sB4 = (const float*)d_in[8];
    const float* sW5 = (const float*)d_in[9];
    const float* sB5 = (const float*)d_in[10];
    const float* tW1 = (const float*)d_in[11];
    const float* tB1 = (const float*)d_in[12];
    const float* tW2 = (const float*)d_in[13];
    const float* tB2 = (const float*)d_in[14];
    const float* tW3 = (const float*)d_in[15];
    const float* tB3 = (const float*)d_in[16];
    const float* tW4 = (const float*)d_in[17];
    const float* tB4 = (const float*)d_in[18];
    const float* tW5 = (const float*)d_in[19];
    const float* tB5 = (const float*)d_in[20];

    cudaFuncSetAttribute(realnvp_kernel, cudaFuncAttributeMaxDynamicSharedMemorySize,
                         SMEM_DYN);

    prepack_kernel<<<(NMAT * 8192 + 255) / 256, 256>>>(sW2, sW3, sW4, tW2, tW3, tW4);
    realnvp_kernel<<<BSZ / MT, NTHR, SMEM_DYN>>>(
        X, sW1, sB1, sB2, sB3, sB4, sW5, sB5,
        tW1, tB1, tB2, tB3, tB4, tW5, tB5, (float*)d_out);
}

// round 8
// speedup vs baseline: 2.0563x; 1.0737x over previous
#include <cuda_runtime.h>
#include <cuda_fp16.h>
#include <cstdint>

#define NTHR 256
#define MT 64
#define BSZ 131072
#define NMAT 36
#define TOTAL_SLABS 144      // 36 mats x 4 slabs (K=64 each)
#define SLAB_HALVES 16384    // 64k x 256n fp16
#define SLAB_BYTES 32768
#define STR2 72              // half2 words per act row; 72 mod 32 = 8 -> conflict-free

// smem byte offsets
#define OFF_WBUF 0                      // 2 x 32KB
#define OFF_ACT  65536                  // 128 rows x 72 words x 4B = 36864
#define OFF_BIAS 102400
#define OFF_W1S  103424
#define OFF_B1S  104448
#define OFF_W5S  105472
#define OFF_XV   106496                 // 64 x 2 floats
#define OFF_PP   107008                 // 4 x 64 floats
#define OFF_SARR 108032
#define OFF_TARR 108288
#define SMEM_DYN 108544

__device__ __half g_wpack[NMAT * 65536];

// ---------------------------------------------------------------------------
__device__ __forceinline__ void cpasync16(uint32_t dst, const void* src) {
    asm volatile("cp.async.cg.shared.global [%0], [%1], 16;" :: "r"(dst), "l"(src));
}
__device__ __forceinline__ void mma_f16(float acc[4], uint4 a, uint32_t b0, uint32_t b1) {
    asm volatile(
        "mma.sync.aligned.m16n8k16.row.col.f32.f16.f16.f32 "
        "{%0,%1,%2,%3}, {%4,%5,%6,%7}, {%8,%9}, {%0,%1,%2,%3};"
        : "+f"(acc[0]), "+f"(acc[1]), "+f"(acc[2]), "+f"(acc[3])
        : "r"(a.x), "r"(a.y), "r"(a.z), "r"(a.w), "r"(b0), "r"(b1));
}
__device__ __forceinline__ uint32_t h2u(float lo, float hi) {
    __half2 h = __floats2half2_rn(lo, hi);
    return *(uint32_t*)&h;
}

// ---------------------------------------------------------------------------
// prepack: W[k][n] fp32 -> fp16, A-fragment order for m16n8k16 with k-permutation
// kappa: slot 2j->feat j, 2j+1->j+8, 8+2j->j+4, 9+2j->j+12 (within 16-block).
// Slab = K=64 (16384 halves). One thread builds one lane's uint4 (8 halves).
// ---------------------------------------------------------------------------
__global__ void prepack_kernel(const float* sW2, const float* sW3, const float* sW4,
                               const float* tW2, const float* tW3, const float* tW4) {
    int idx = blockIdx.x * blockDim.x + threadIdx.x;
    if (idx >= NMAT * 8192) return;     // one uint4 (8 halves) per thread
    int lane = idx & 31;
    int mt   = (idx >> 5) & 15;
    int kc   = (idx >> 9) & 3;
    int slab = (idx >> 11) & 3;
    int mat  = idx >> 13;

    int st = mat / 18, rem = mat % 18, l = rem / 3, g = rem % 3;
    const float* src;
    switch (st * 3 + g) {
        case 0: src = sW2; break;
        case 1: src = sW3; break;
        case 2: src = sW4; break;
        case 3: src = tW2; break;
        case 4: src = tW3; break;
        default: src = tW4; break;
    }
    src += l * 65536;

    int v = lane & 3, mlow = lane >> 2;
    int kb = slab * 64 + kc * 16;       // k base of this 16-chunk
    int nb = mt * 16;                   // feature (A row) base

    uint4 o;
    o.x = h2u(src[(kb + v)     * 256 + nb + mlow],     src[(kb + v + 8)  * 256 + nb + mlow]);
    o.y = h2u(src[(kb + v)     * 256 + nb + mlow + 8], src[(kb + v + 8)  * 256 + nb + mlow + 8]);
    o.z = h2u(src[(kb + v + 4) * 256 + nb + mlow],     src[(kb + v + 12) * 256 + nb + mlow]);
    o.w = h2u(src[(kb + v + 4) * 256 + nb + mlow + 8], src[(kb + v + 12) * 256 + nb + mlow + 8]);

    *(uint4*)(g_wpack + (size_t)mat * 65536 + slab * SLAB_HALVES
              + ((kc * 16 + mt) * 32 + lane) * 8) = o;
}

// ---------------------------------------------------------------------------
__global__ void __launch_bounds__(NTHR, 2)
realnvp_kernel(const float* __restrict__ X,
               const float* __restrict__ sW1, const float* __restrict__ sB1,
               const float* __restrict__ sB2, const float* __restrict__ sB3,
               const float* __restrict__ sB4, const float* __restrict__ sW5,
               const float* __restrict__ sB5,
               const float* __restrict__ tW1, const float* __restrict__ tB1,
               const float* __restrict__ tB2, const float* __restrict__ tB3,
               const float* __restrict__ tB4, const float* __restrict__ tW5,
               const float* __restrict__ tB5,
               float* __restrict__ out) {
    extern __shared__ char base[];
    uint32_t* actu   = (uint32_t*)(base + OFF_ACT);   // half2 words [row][STR2]
    float*    bias_s = (float*)(base + OFF_BIAS);
    float*    w1s    = (float*)(base + OFF_W1S);
    float*    b1s    = (float*)(base + OFF_B1S);
    float*    w5s    = (float*)(base + OFF_W5S);
    float*    xv     = (float*)(base + OFF_XV);
    float*    pp     = (float*)(base + OFF_PP);       // [4][64]
    float*    sarr   = (float*)(base + OFF_SARR);
    float*    tarr   = (float*)(base + OFF_TARR);
    uint32_t  wbuf_sh = (uint32_t)__cvta_generic_to_shared(base + OFF_WBUF);

    int tid  = threadIdx.x;
    int wid  = tid >> 5, lane = tid & 31;
    int wm   = wid >> 1;          // 0..3 feature tiles of 64
    int wn   = wid & 1;           // 0..1 sample tiles of 32
    int u    = lane >> 2;         // 0..7
    int v    = lane & 3;          // 0..3
    int gbase = blockIdx.x * MT;

    float ldet = 0.f;
    if (tid < MT) {
        float2 xx = *(const float2*)&X[(gbase + tid) * 2];
        xv[tid * 2 + 0] = logf(xx.x / (1.f - xx.x));
        xv[tid * 2 + 1] = logf(xx.y / (1.f - xx.y));
    }

    // ---- weight slab prefetch (2-buffer ring of 32KB) ----
    auto prefetch = [&](int q) {
        int qq = (q >= TOTAL_SLABS) ? q - TOTAL_SLABS : q;
        int j = qq >> 2, sl = qq & 3;
        int li = 5 - j / 6;
        int r6 = j % 6;
        int mat = ((r6 / 3) * 6 + li) * 3 + (r6 % 3);
        const __half* src = g_wpack + (size_t)mat * 65536 + sl * SLAB_HALVES + tid * 8;
        uint32_t dst = wbuf_sh + (uint32_t)(q & 1) * SLAB_BYTES + tid * 16;
#pragma unroll
        for (int it = 0; it < 8; it++)
            cpasync16(dst + it * 4096, src + it * 2048);
        asm volatile("cp.async.commit_group;");
    };

    prefetch(0);

    // ---- layer0: act row r holds features (16t+j, 16t+j+8), t=r>>3, j=r&7 ----
    auto layer0 = [&](const float* w1row, const float* b1, int cdim) {
        w1s[tid] = w1row[tid];
        b1s[tid] = b1[tid];
        __syncthreads();
        int r = tid >> 1;
        int k0 = ((r >> 3) << 4) + (r & 7), k1 = k0 + 8;
        float w0 = w1s[k0], bb0 = b1s[k0];
        float w1v = w1s[k1], bb1 = b1s[k1];
        int sbase = (tid & 1) * 32;
#pragma unroll 2
        for (int i = 0; i < 8; i++) {
            uint4 wrds;
            int s = sbase + i * 4;
            float x0 = xv[(s + 0) * 2 + cdim], x1 = xv[(s + 1) * 2 + cdim];
            float x2 = xv[(s + 2) * 2 + cdim], x3 = xv[(s + 3) * 2 + cdim];
            wrds.x = h2u(fmaxf(fmaf(x0, w0, bb0), 0.f), fmaxf(fmaf(x0, w1v, bb1), 0.f));
            wrds.y = h2u(fmaxf(fmaf(x1, w0, bb0), 0.f), fmaxf(fmaf(x1, w1v, bb1), 0.f));
            wrds.z = h2u(fmaxf(fmaf(x2, w0, bb0), 0.f), fmaxf(fmaf(x2, w1v, bb1), 0.f));
            wrds.w = h2u(fmaxf(fmaf(x3, w0, bb0), 0.f), fmaxf(fmaf(x3, w1v, bb1), 0.f));
            *(uint4*)&actu[r * STR2 + s] = wrds;
        }
        __syncthreads();
    };

    // ---- one 64x256 @ 256x256 GEMM (4 K=64 slabs); epilogue writes act or W5 dot ----
    auto gemm = [&](int gc, const float* bias, bool fuse,
                    const float* w5col, float b5, bool is_s) {
        bias_s[tid] = bias[tid];
        if (fuse) w5s[tid] = w5col[tid * 2];
        float acc[4][4][4];
#pragma unroll
        for (int a = 0; a < 4; a++)
#pragma unroll
            for (int b = 0; b < 4; b++)
#pragma unroll
                for (int q = 0; q < 4; q++) acc[a][b][q] = 0.f;

#pragma unroll 1
        for (int sl = 0; sl < 4; sl++) {
            int q = gc * 4 + sl;
            asm volatile("cp.async.wait_group 0;");
            __syncthreads();             // slab q visible; buf (q+1)&1 free
            prefetch(q + 1);
            const __half* wb = (const __half*)(base + OFF_WBUF + (q & 1) * SLAB_BYTES);
#pragma unroll
            for (int kc = 0; kc < 4; kc++) {
                uint4 a[4];
#pragma unroll
                for (int mf = 0; mf < 4; mf++)
                    a[mf] = *(const uint4*)(wb + ((kc * 16 + wm * 4 + mf) * 32 + lane) * 8);
                int kg = sl * 4 + kc;
                const uint32_t* p0 = actu + (kg * 8 + v) * STR2 + wn * 32 + u;
                uint32_t b0[4], b1[4];
#pragma unroll
                for (int nf = 0; nf < 4; nf++) {
                    b0[nf] = p0[nf * 8];
                    b1[nf] = p0[4 * STR2 + nf * 8];
                }
#pragma unroll
                for (int mf = 0; mf < 4; mf++)
#pragma unroll
                    for (int nf = 0; nf < 4; nf++)
                        mma_f16(acc[mf][nf], a[mf], b0[nf], b1[nf]);
            }
        }
        __syncthreads();                 // all reads of act done before overwrite

        if (!fuse) {
            // bias + relu + fp16 pair store: row = 8*(wm*4+mf) + u holds (f0, f0+8)
#pragma unroll
            for (int mf = 0; mf < 4; mf++) {
                int f0 = wm * 64 + mf * 16 + u;
                int row = (wm * 4 + mf) * 8 + u;
                float bx = bias_s[f0], by = bias_s[f0 + 8];
#pragma unroll
                for (int nf = 0; nf < 4; nf++) {
                    int s0 = wn * 32 + nf * 8 + v * 2;
                    uint2 wr;
                    wr.x = h2u(fmaxf(acc[mf][nf][0] + bx, 0.f),
                               fmaxf(acc[mf][nf][2] + by, 0.f));
                    wr.y = h2u(fmaxf(acc[mf][nf][1] + bx, 0.f),
                               fmaxf(acc[mf][nf][3] + by, 0.f));
                    *(uint2*)&actu[row * STR2 + s0] = wr;
                }
            }
            __syncthreads();
        } else {
            // fused H->1 dot: p[s] = sum_f relu(acc+bias) * w5[f]
            float p[4][2];
#pragma unroll
            for (int nf = 0; nf < 4; nf++) { p[nf][0] = 0.f; p[nf][1] = 0.f; }
#pragma unroll
            for (int mf = 0; mf < 4; mf++) {
                int f0 = wm * 64 + mf * 16 + u;
                float bx = bias_s[f0], by = bias_s[f0 + 8];
                float wa = w5s[f0],   wb5 = w5s[f0 + 8];
#pragma unroll
                for (int nf = 0; nf < 4; nf++) {
                    float v0 = fmaxf(acc[mf][nf][0] + bx, 0.f);
                    float v1 = fmaxf(acc[mf][nf][1] + bx, 0.f);
                    float v2 = fmaxf(acc[mf][nf][2] + by, 0.f);
                    float v3 = fmaxf(acc[mf][nf][3] + by, 0.f);
                    p[nf][0] = fmaf(v0, wa, fmaf(v2, wb5, p[nf][0]));
                    p[nf][1] = fmaf(v1, wa, fmaf(v3, wb5, p[nf][1]));
                }
            }
#pragma unroll
            for (int nf = 0; nf < 4; nf++) {
#pragma unroll
                for (int j = 0; j < 2; j++) {
                    float t = p[nf][j];
                    t += __shfl_down_sync(0xffffffffu, t, 16);
                    t += __shfl_down_sync(0xffffffffu, t, 8);
                    t += __shfl_down_sync(0xffffffffu, t, 4);
                    if (lane < 4)
                        pp[wm * 64 + wn * 32 + nf * 8 + lane * 2 + j] = t;
                }
            }
            __syncthreads();
            if (tid < MT) {
                float o = pp[tid] + pp[64 + tid] + pp[128 + tid] + pp[192 + tid] + b5;
                if (is_s) sarr[tid] = tanhf(o);
                else      tarr[tid] = o;
            }
            __syncthreads();
        }
    };

    // ---- main flow: 6 coupling layers, reversed ----
    int gc = 0;
    for (int i = 5; i >= 0; i--) {
        int cdim = (i & 1) ? 0 : 1;
        int other = 1 - cdim;

        layer0(sW1 + i * 512 + cdim * 256, sB1 + i * 256, cdim);
        gemm(gc++, sB2 + i * 256, false, 0, 0.f, false);
        gemm(gc++, sB3 + i * 256, false, 0, 0.f, false);
        gemm(gc++, sB4 + i * 256, true, sW5 + i * 512 + other, sB5[i * 2 + other], true);

        layer0(tW1 + i * 512 + cdim * 256, tB1 + i * 256, cdim);
        gemm(gc++, tB2 + i * 256, false, 0, 0.f, false);
        gemm(gc++, tB3 + i * 256, false, 0, 0.f, false);
        gemm(gc++, tB4 + i * 256, true, tW5 + i * 512 + other, tB5[i * 2 + other], false);

        if (tid < MT) {
            float sv = sarr[tid], tv = tarr[tid];
            xv[tid * 2 + other] = (xv[tid * 2 + other] - tv) * expf(-sv);
            ldet -= sv;
        }
        __syncthreads();
    }

    if (tid < MT) {
        int g = gbase + tid;
        float2 o;
        o.x = 1.f / (1.f + expf(-xv[tid * 2 + 0]));
        o.y = 1.f / (1.f + expf(-xv[tid * 2 + 1]));
        *(float2*)&out[g * 2] = o;
        out[2 * BSZ + g] = ldet;
    }
    asm volatile("cp.async.wait_group 0;");
}

// ---------------------------------------------------------------------------
extern "C" void kernel_launch(void* const* d_in, const int* in_sizes, int n_in,
                              void* d_out, int out_size) {
    const float* X   = (const float*)d_in[0];
    const float* sW1 = (const float*)d_in[1];
    const float* sB1 = (const float*)d_in[2];
    const float* sW2 = (const float*)d_in[3];
    const float* sB2 = (const float*)d_in[4];
    const float* sW3 = (const float*)d_in[5];
    const float* sB3 = (const float*)d_in[6];
    const float* sW4 = (const float*)d_in[7];
    const float* sB4 = (const float*)d_in[8];
    const float* sW5 = (const float*)d_in[9];
    const float* sB5 = (const float*)d_in[10];
    const float* tW1 = (const float*)d_in[11];
    const float* tB1 = (const float*)d_in[12];
    const float* tW2 = (const float*)d_in[13];
    const float* tB2 = (const float*)d_in[14];
    const float* tW3 = (const float*)d_in[15];
    const float* tB3 = (const float*)d_in[16];
    const float* tW4 = (const float*)d_in[17];
    const float* tB4 = (const float*)d_in[18];
    const float* tW5 = (const float*)d_in[19];
    const float* tB5 = (const float*)d_in[20];

    cudaFuncSetAttribute(realnvp_kernel, cudaFuncAttributeMaxDynamicSharedMemorySize,
                         SMEM_DYN);

    prepack_kernel<<<(NMAT * 8192 + 255) / 256, 256>>>(sW2, sW3, sW4, tW2, tW3, tW4);
    realnvp_kernel<<<BSZ / MT, NTHR, SMEM_DYN>>>(
        X, sW1, sB1, sB2, sB3, sB4, sW5, sB5,
        tW1, tB1, tB2, tB3, tB4, tW5, tB5, (float*)d_out);
}

// round 9
// speedup vs baseline: 2.0992x; 1.0208x over previous
#include <cuda_runtime.h>
#include <cuda_fp16.h>
#include <cstdint>

#define NTHR 128
#define MT 64
#define BSZ 131072
#define NMAT 36
#define TOTAL_SLABS 144      // 36 mats x 4 slabs (K=64 each)
#define SLAB_HALVES 16384
#define SLAB_BYTES 32768
#define STR2 72              // half2 words per act row; 72 mod 32 = 8 -> conflict-free

// smem byte offsets
#define OFF_WBUF 0                      // 2 x 32KB
#define OFF_ACT  65536                  // 128 rows x 72 words x 4B = 36864
#define OFF_BIAS 102400                 // 2 x 256 floats (gc-parity double buffer)
#define OFF_W1S  104448
#define OFF_B1S  105472
#define OFF_W5S  106496
#define OFF_XV   107520                 // 64 x 2 floats
#define OFF_PP   108032                 // 4 x 64 floats
#define OFF_SARR 109056
#define OFF_TARR 109312
#define SMEM_DYN 109568

__device__ __half g_wpack[NMAT * 65536];

// ---------------------------------------------------------------------------
__device__ __forceinline__ void cpasync16(uint32_t dst, const void* src) {
    asm volatile("cp.async.cg.shared.global [%0], [%1], 16;" :: "r"(dst), "l"(src));
}
__device__ __forceinline__ void mma_f16(float acc[4], uint4 a, uint32_t b0, uint32_t b1) {
    asm volatile(
        "mma.sync.aligned.m16n8k16.row.col.f32.f16.f16.f32 "
        "{%0,%1,%2,%3}, {%4,%5,%6,%7}, {%8,%9}, {%0,%1,%2,%3};"
        : "+f"(acc[0]), "+f"(acc[1]), "+f"(acc[2]), "+f"(acc[3])
        : "r"(a.x), "r"(a.y), "r"(a.z), "r"(a.w), "r"(b0), "r"(b1));
}
__device__ __forceinline__ uint32_t h2u(float lo, float hi) {
    __half2 h = __floats2half2_rn(lo, hi);
    return *(uint32_t*)&h;
}

// ---------------------------------------------------------------------------
// prepack (unchanged layout): W[k][n] fp32 -> fp16, A-fragment order for
// m16n8k16 with k-permutation kappa (pairs (j, j+8) within each 16-block).
// ---------------------------------------------------------------------------
__global__ void prepack_kernel(const float* sW2, const float* sW3, const float* sW4,
                               const float* tW2, const float* tW3, const float* tW4) {
    int idx = blockIdx.x * blockDim.x + threadIdx.x;
    if (idx >= NMAT * 8192) return;
    int lane = idx & 31;
    int mt   = (idx >> 5) & 15;
    int kc   = (idx >> 9) & 3;
    int slab = (idx >> 11) & 3;
    int mat  = idx >> 13;

    int st = mat / 18, rem = mat % 18, l = rem / 3, g = rem % 3;
    const float* src;
    switch (st * 3 + g) {
        case 0: src = sW2; break;
        case 1: src = sW3; break;
        case 2: src = sW4; break;
        case 3: src = tW2; break;
        case 4: src = tW3; break;
        default: src = tW4; break;
    }
    src += l * 65536;

    int v = lane & 3, mlow = lane >> 2;
    int kb = slab * 64 + kc * 16;
    int nb = mt * 16;

    uint4 o;
    o.x = h2u(src[(kb + v)     * 256 + nb + mlow],     src[(kb + v + 8)  * 256 + nb + mlow]);
    o.y = h2u(src[(kb + v)     * 256 + nb + mlow + 8], src[(kb + v + 8)  * 256 + nb + mlow + 8]);
    o.z = h2u(src[(kb + v + 4) * 256 + nb + mlow],     src[(kb + v + 12) * 256 + nb + mlow]);
    o.w = h2u(src[(kb + v + 4) * 256 + nb + mlow + 8], src[(kb + v + 12) * 256 + nb + mlow + 8]);

    *(uint4*)(g_wpack + (size_t)mat * 65536 + slab * SLAB_HALVES
              + ((kc * 16 + mt) * 32 + lane) * 8) = o;
}

// ---------------------------------------------------------------------------
__global__ void __launch_bounds__(NTHR, 2)
realnvp_kernel(const float* __restrict__ X,
               const float* __restrict__ sW1, const float* __restrict__ sB1,
               const float* __restrict__ sB2, const float* __restrict__ sB3,
               const float* __restrict__ sB4, const float* __restrict__ sW5,
               const float* __restrict__ sB5,
               const float* __restrict__ tW1, const float* __restrict__ tB1,
               const float* __restrict__ tB2, const float* __restrict__ tB3,
               const float* __restrict__ tB4, const float* __restrict__ tW5,
               const float* __restrict__ tB5,
               float* __restrict__ out) {
    extern __shared__ char base[];
    uint32_t* actu   = (uint32_t*)(base + OFF_ACT);   // half2 words [row][STR2]
    float*    bias2  = (float*)(base + OFF_BIAS);     // [2][256]
    float*    w1s    = (float*)(base + OFF_W1S);
    float*    b1s    = (float*)(base + OFF_B1S);
    float*    w5s    = (float*)(base + OFF_W5S);
    float*    xv     = (float*)(base + OFF_XV);
    float*    pp     = (float*)(base + OFF_PP);       // [4][64]
    float*    sarr   = (float*)(base + OFF_SARR);
    float*    tarr   = (float*)(base + OFF_TARR);
    uint32_t  wbuf_sh = (uint32_t)__cvta_generic_to_shared(base + OFF_WBUF);

    int tid  = threadIdx.x;
    int wid  = tid >> 5, lane = tid & 31;     // wid = feature tile of 64 (0..3)
    int u    = lane >> 2;                     // 0..7
    int v    = lane & 3;                      // 0..3
    int gbase = blockIdx.x * MT;

    float ldet = 0.f;
    if (tid < MT) {
        float2 xx = *(const float2*)&X[(gbase + tid) * 2];
        xv[tid * 2 + 0] = logf(xx.x / (1.f - xx.x));
        xv[tid * 2 + 1] = logf(xx.y / (1.f - xx.y));
    }

    // ---- weight slab prefetch (2-buffer ring of 32KB; 256B per thread) ----
    auto prefetch = [&](int q) {
        int qq = (q >= TOTAL_SLABS) ? q - TOTAL_SLABS : q;
        int j = qq >> 2, sl = qq & 3;
        int li = 5 - j / 6;
        int r6 = j % 6;
        int mat = ((r6 / 3) * 6 + li) * 3 + (r6 % 3);
        const __half* src = g_wpack + (size_t)mat * 65536 + sl * SLAB_HALVES + tid * 8;
        uint32_t dst = wbuf_sh + (uint32_t)(q & 1) * SLAB_BYTES + tid * 16;
#pragma unroll
        for (int it = 0; it < 16; it++)
            cpasync16(dst + it * 2048, src + it * 1024);
        asm volatile("cp.async.commit_group;");
    };

    prefetch(0);

    // ---- layer0: thread = one k-pair row (128 rows), 64 samples each ----
    auto layer0 = [&](const float* w1row, const float* b1, int cdim) {
        if (tid < 128) { w1s[tid] = w1row[tid]; b1s[tid] = b1[tid]; }
        else { w1s[tid + 128] = w1row[tid + 128]; }
        w1s[((tid + 64) & 127) + ((tid < 64) ? 128 : 0)] =
            w1row[((tid + 64) & 127) + ((tid < 64) ? 128 : 0)];   // fill all 256
        b1s[tid + ((tid < 128) ? 128 : -128) * 0] = b1s[tid];      // no-op keep
        // simpler: just load both halves explicitly
        w1s[tid] = w1row[tid]; w1s[tid + 128] = w1row[tid + 128];
        b1s[tid] = b1[tid];    b1s[tid + 128] = b1[tid + 128];
        __syncthreads();
        int r = tid;                         // 0..127
        int k0 = ((r >> 3) << 4) + (r & 7), k1 = k0 + 8;
        float w0 = w1s[k0], bb0 = b1s[k0];
        float w1v = w1s[k1], bb1 = b1s[k1];
#pragma unroll 4
        for (int i = 0; i < 16; i++) {
            uint4 wrds;
            int s = i * 4;
            float x0 = xv[(s + 0) * 2 + cdim], x1 = xv[(s + 1) * 2 + cdim];
            float x2 = xv[(s + 2) * 2 + cdim], x3 = xv[(s + 3) * 2 + cdim];
            wrds.x = h2u(fmaxf(fmaf(x0, w0, bb0), 0.f), fmaxf(fmaf(x0, w1v, bb1), 0.f));
            wrds.y = h2u(fmaxf(fmaf(x1, w0, bb0), 0.f), fmaxf(fmaf(x1, w1v, bb1), 0.f));
            wrds.z = h2u(fmaxf(fmaf(x2, w0, bb0), 0.f), fmaxf(fmaf(x2, w1v, bb1), 0.f));
            wrds.w = h2u(fmaxf(fmaf(x3, w0, bb0), 0.f), fmaxf(fmaf(x3, w1v, bb1), 0.f));
            *(uint4*)&actu[r * STR2 + s] = wrds;
        }
        // no trailing sync: next gemm's first slab-sync covers act visibility
    };

    // ---- one 64x256 @ 256x256 GEMM; warp tile m64(features) x n64(samples) ----
    auto gemm = [&](int gc, const float* biasg, bool fuse,
                    const float* w5col, float b5, bool is_s) {
        float* bias_c = bias2 + (gc & 1) * 256;
        bias_c[tid] = biasg[tid];
        bias_c[tid + 128] = biasg[tid + 128];
        if (fuse) { w5s[tid] = w5col[tid * 2]; w5s[tid + 128] = w5col[(tid + 128) * 2]; }

        float acc[4][8][4];
#pragma unroll
        for (int a = 0; a < 4; a++)
#pragma unroll
            for (int b = 0; b < 8; b++)
#pragma unroll
                for (int q = 0; q < 4; q++) acc[a][b][q] = 0.f;

#pragma unroll 1
        for (int sl = 0; sl < 4; sl++) {
            int q = gc * 4 + sl;
            asm volatile("cp.async.wait_group 0;");
            __syncthreads();             // slab q visible; buf (q+1)&1 free; act ready
            prefetch(q + 1);
            const __half* wb = (const __half*)(base + OFF_WBUF + (q & 1) * SLAB_BYTES);
#pragma unroll
            for (int kc = 0; kc < 4; kc++) {
                uint4 a[4];
#pragma unroll
                for (int mf = 0; mf < 4; mf++)
                    a[mf] = *(const uint4*)(wb + ((kc * 16 + wid * 4 + mf) * 32 + lane) * 8);
                int kg = sl * 4 + kc;
                const uint32_t* p0 = actu + (kg * 8 + v) * STR2 + u;
                uint32_t b0[8], b1[8];
#pragma unroll
                for (int nf = 0; nf < 8; nf++) {
                    b0[nf] = p0[nf * 8];
                    b1[nf] = p0[4 * STR2 + nf * 8];
                }
#pragma unroll
                for (int mf = 0; mf < 4; mf++)
#pragma unroll
                    for (int nf = 0; nf < 8; nf++)
                        mma_f16(acc[mf][nf], a[mf], b0[nf], b1[nf]);
            }
        }
        __syncthreads();                 // all reads of act done before overwrite

        if (!fuse) {
            // bias + relu + fp16 pair store; row = (wid*4+mf)*8+u holds (f0, f0+8)
#pragma unroll
            for (int mf = 0; mf < 4; mf++) {
                int f0 = wid * 64 + mf * 16 + u;
                int row = (wid * 4 + mf) * 8 + u;
                float bx = bias_c[f0], by = bias_c[f0 + 8];
#pragma unroll
                for (int nf = 0; nf < 8; nf++) {
                    int s0 = nf * 8 + v * 2;
                    uint2 wr;
                    wr.x = h2u(fmaxf(acc[mf][nf][0] + bx, 0.f),
                               fmaxf(acc[mf][nf][2] + by, 0.f));
                    wr.y = h2u(fmaxf(acc[mf][nf][1] + bx, 0.f),
                               fmaxf(acc[mf][nf][3] + by, 0.f));
                    *(uint2*)&actu[row * STR2 + s0] = wr;
                }
            }
            // no trailing sync (bias double-buffered; act covered by next slab-sync)
        } else {
            // fused H->1 dot
            float p[8][2];
#pragma unroll
            for (int nf = 0; nf < 8; nf++) { p[nf][0] = 0.f; p[nf][1] = 0.f; }
#pragma unroll
            for (int mf = 0; mf < 4; mf++) {
                int f0 = wid * 64 + mf * 16 + u;
                float bx = bias_c[f0], by = bias_c[f0 + 8];
                float wa = w5s[f0],   wb5 = w5s[f0 + 8];
#pragma unroll
                for (int nf = 0; nf < 8; nf++) {
                    float v0 = fmaxf(acc[mf][nf][0] + bx, 0.f);
                    float v1 = fmaxf(acc[mf][nf][1] + bx, 0.f);
                    float v2 = fmaxf(acc[mf][nf][2] + by, 0.f);
                    float v3 = fmaxf(acc[mf][nf][3] + by, 0.f);
                    p[nf][0] = fmaf(v0, wa, fmaf(v2, wb5, p[nf][0]));
                    p[nf][1] = fmaf(v1, wa, fmaf(v3, wb5, p[nf][1]));
                }
            }
#pragma unroll
            for (int nf = 0; nf < 8; nf++) {
#pragma unroll
                for (int j = 0; j < 2; j++) {
                    float t = p[nf][j];
                    t += __shfl_down_sync(0xffffffffu, t, 16);
                    t += __shfl_down_sync(0xffffffffu, t, 8);
                    t += __shfl_down_sync(0xffffffffu, t, 4);
                    if (lane < 4)
                        pp[wid * 64 + nf * 8 + lane * 2 + j] = t;
                }
            }
            __syncthreads();
            if (tid < MT) {
                float o = pp[tid] + pp[64 + tid] + pp[128 + tid] + pp[192 + tid] + b5;
                if (is_s) sarr[tid] = tanhf(o);
                else      tarr[tid] = o;
            }
        }
    };

    // ---- main flow: 6 coupling layers, reversed ----
    int gc = 0;
    for (int i = 5; i >= 0; i--) {
        int cdim = (i & 1) ? 0 : 1;
        int other = 1 - cdim;

        layer0(sW1 + i * 512 + cdim * 256, sB1 + i * 256, cdim);
        gemm(gc++, sB2 + i * 256, false, 0, 0.f, false);
        gemm(gc++, sB3 + i * 256, false, 0, 0.f, false);
        gemm(gc++, sB4 + i * 256, true, sW5 + i * 512 + other, sB5[i * 2 + other], true);

        layer0(tW1 + i * 512 + cdim * 256, tB1 + i * 256, cdim);
        gemm(gc++, tB2 + i * 256, false, 0, 0.f, false);
        gemm(gc++, tB3 + i * 256, false, 0, 0.f, false);
        gemm(gc++, tB4 + i * 256, true, tW5 + i * 512 + other, tB5[i * 2 + other], false);

        // coupling update (same-tid as sarr/tarr writers; no sync needed)
        if (tid < MT) {
            float sv = sarr[tid], tv = tarr[tid];
            xv[tid * 2 + other] = (xv[tid * 2 + other] - tv) * expf(-sv);
            ldet -= sv;
        }
        __syncthreads();    // xv visible to next layer0 / output
    }

    if (tid < MT) {
        int g = gbase + tid;
        float2 o;
        o.x = 1.f / (1.f + expf(-xv[tid * 2 + 0]));
        o.y = 1.f / (1.f + expf(-xv[tid * 2 + 1]));
        *(float2*)&out[g * 2] = o;
        out[2 * BSZ + g] = ldet;
    }
    asm volatile("cp.async.wait_group 0;");
}

// ---------------------------------------------------------------------------
extern "C" void kernel_launch(void* const* d_in, const int* in_sizes, int n_in,
                              void* d_out, int out_size) {
    const float* X   = (const float*)d_in[0];
    const float* sW1 = (const float*)d_in[1];
    const float* sB1 = (const float*)d_in[2];
    const float* sW2 = (const float*)d_in[3];
    const float* sB2 = (const float*)d_in[4];
    const float* sW3 = (const float*)d_in[5];
    const float* sB3 = (const float*)d_in[6];
    const float* sW4 = (const float*)d_in[7];
    const float* sB4 = (const float*)d_in[8];
    const float* sW5 = (const float*)d_in[9];
    const float* sB5 = (const float*)d_in[10];
    const float* tW1 = (const float*)d_in[11];
    const float* tB1 = (const float*)d_in[12];
    const float* tW2 = (const float*)d_in[13];
    const float* tB2 = (const float*)d_in[14];
    const float* tW3 = (const float*)d_in[15];
    const float* tB3 = (const float*)d_in[16];
    const float* tW4 = (const float*)d_in[17];
    const float* tB4 = (const float*)d_in[18];
    const float* tW5 = (const float*)d_in[19];
    const float* tB5 = (const float*)d_in[20];

    cudaFuncSetAttribute(realnvp_kernel, cudaFuncAttributeMaxDynamicSharedMemorySize,
                         SMEM_DYN);

    prepack_kernel<<<(NMAT * 8192 + 255) / 256, 256>>>(sW2, sW3, sW4, tW2, tW3, tW4);
    realnvp_kernel<<<BSZ / MT, NTHR, SMEM_DYN>>>(
        X, sW1, sB1, sB2, sB3, sB4, sW5, sB5,
        tW1, tB1, tB2, tB3, tB4, tW5, tB5, (float*)d_out);
}

// round 10
// speedup vs baseline: 2.0994x; 1.0001x over previous
#include <cuda_runtime.h>
#include <cuda_fp16.h>
#include <cstdint>

#define NTHR 128
#define MT 64
#define BSZ 131072
#define NMAT 36
#define TOTAL_SLABS 288      // 36 mats x 8 slabs (K=32 each)
#define SLAB_HALVES 8192
#define SLAB_BYTES 16384
#define NBUF 4
#define STR2 72              // half2 words per act row; 72 mod 32 = 8 -> conflict-free

// smem byte offsets
#define OFF_WBUF 0                      // 4 x 16KB
#define OFF_ACT  65536                  // 128 rows x 72 words x 4B = 36864
#define OFF_BIAS 102400                 // 2 x 256 floats (gc-parity double buffer)
#define OFF_W1S  104448
#define OFF_B1S  105472
#define OFF_W5S  106496
#define OFF_XV   107520                 // 64 x 2 floats
#define OFF_PP   108032                 // 4 x 64 floats
#define OFF_SARR 109056
#define OFF_TARR 109312
#define SMEM_DYN 109568

__device__ __half g_wpack[NMAT * 65536];

// ---------------------------------------------------------------------------
__device__ __forceinline__ void cpasync16(uint32_t dst, const void* src) {
    asm volatile("cp.async.cg.shared.global [%0], [%1], 16;" :: "r"(dst), "l"(src));
}
__device__ __forceinline__ void mma_f16(float acc[4], uint4 a, uint32_t b0, uint32_t b1) {
    asm volatile(
        "mma.sync.aligned.m16n8k16.row.col.f32.f16.f16.f32 "
        "{%0,%1,%2,%3}, {%4,%5,%6,%7}, {%8,%9}, {%0,%1,%2,%3};"
        : "+f"(acc[0]), "+f"(acc[1]), "+f"(acc[2]), "+f"(acc[3])
        : "r"(a.x), "r"(a.y), "r"(a.z), "r"(a.w), "r"(b0), "r"(b1));
}
__device__ __forceinline__ uint32_t h2u(float lo, float hi) {
    __half2 h = __floats2half2_rn(lo, hi);
    return *(uint32_t*)&h;
}

// ---------------------------------------------------------------------------
// prepack: W[k][n] fp32 -> fp16, A-fragment order for m16n8k16 with
// k-permutation kappa (pairs (j, j+8) within each 16-block). Slab = K=32.
// ---------------------------------------------------------------------------
__global__ void prepack_kernel(const float* sW2, const float* sW3, const float* sW4,
                               const float* tW2, const float* tW3, const float* tW4) {
    int idx = blockIdx.x * blockDim.x + threadIdx.x;
    if (idx >= NMAT * 8192) return;
    int lane = idx & 31;
    int mt   = (idx >> 5) & 15;
    int kc   = (idx >> 9) & 1;
    int slab = (idx >> 10) & 7;
    int mat  = idx >> 13;

    int st = mat / 18, rem = mat % 18, l = rem / 3, g = rem % 3;
    const float* src;
    switch (st * 3 + g) {
        case 0: src = sW2; break;
        case 1: src = sW3; break;
        case 2: src = sW4; break;
        case 3: src = tW2; break;
        case 4: src = tW3; break;
        default: src = tW4; break;
    }
    src += l * 65536;

    int v = lane & 3, mlow = lane >> 2;
    int kb = slab * 32 + kc * 16;
    int nb = mt * 16;

    uint4 o;
    o.x = h2u(src[(kb + v)     * 256 + nb + mlow],     src[(kb + v + 8)  * 256 + nb + mlow]);
    o.y = h2u(src[(kb + v)     * 256 + nb + mlow + 8], src[(kb + v + 8)  * 256 + nb + mlow + 8]);
    o.z = h2u(src[(kb + v + 4) * 256 + nb + mlow],     src[(kb + v + 12) * 256 + nb + mlow]);
    o.w = h2u(src[(kb + v + 4) * 256 + nb + mlow + 8], src[(kb + v + 12) * 256 + nb + mlow + 8]);

    *(uint4*)(g_wpack + (size_t)mat * 65536 + slab * SLAB_HALVES
              + ((kc * 16 + mt) * 32 + lane) * 8) = o;
}

// ---------------------------------------------------------------------------
__global__ void __launch_bounds__(NTHR, 2)
realnvp_kernel(const float* __restrict__ X,
               const float* __restrict__ sW1, const float* __restrict__ sB1,
               const float* __restrict__ sB2, const float* __restrict__ sB3,
               const float* __restrict__ sB4, const float* __restrict__ sW5,
               const float* __restrict__ sB5,
               const float* __restrict__ tW1, const float* __restrict__ tB1,
               const float* __restrict__ tB2, const float* __restrict__ tB3,
               const float* __restrict__ tB4, const float* __restrict__ tW5,
               const float* __restrict__ tB5,
               float* __restrict__ out) {
    extern __shared__ char base[];
    uint32_t* actu   = (uint32_t*)(base + OFF_ACT);   // half2 words [row][STR2]
    float*    bias2  = (float*)(base + OFF_BIAS);     // [2][256]
    float*    w1s    = (float*)(base + OFF_W1S);
    float*    b1s    = (float*)(base + OFF_B1S);
    float*    w5s    = (float*)(base + OFF_W5S);
    float*    xv     = (float*)(base + OFF_XV);
    float*    pp     = (float*)(base + OFF_PP);       // [4][64]
    float*    sarr   = (float*)(base + OFF_SARR);
    float*    tarr   = (float*)(base + OFF_TARR);
    uint32_t  wbuf_sh = (uint32_t)__cvta_generic_to_shared(base + OFF_WBUF);

    int tid  = threadIdx.x;
    int wid  = tid >> 5, lane = tid & 31;     // wid = feature tile of 64 (0..3)
    int u    = lane >> 2;                     // 0..7
    int v    = lane & 3;                      // 0..3
    int gbase = blockIdx.x * MT;

    float ldet = 0.f;
    if (tid < MT) {
        float2 xx = *(const float2*)&X[(gbase + tid) * 2];
        xv[tid * 2 + 0] = logf(xx.x / (1.f - xx.x));
        xv[tid * 2 + 1] = logf(xx.y / (1.f - xx.y));
    }

    // ---- weight slab prefetch (4-buffer ring of 16KB; 128B per thread) ----
    auto prefetch = [&](int q) {
        int qq = (q >= TOTAL_SLABS) ? q - TOTAL_SLABS : q;
        int j = qq >> 3, sl = qq & 7;
        int li = 5 - j / 6;
        int r6 = j % 6;
        int mat = ((r6 / 3) * 6 + li) * 3 + (r6 % 3);
        const __half* src = g_wpack + (size_t)mat * 65536 + sl * SLAB_HALVES + tid * 8;
        uint32_t dst = wbuf_sh + (uint32_t)(q % NBUF) * SLAB_BYTES + tid * 16;
#pragma unroll
        for (int it = 0; it < 8; it++)
            cpasync16(dst + it * 2048, src + it * 1024);
        asm volatile("cp.async.commit_group;");
    };

    prefetch(0);
    prefetch(1);
    prefetch(2);

    // ---- layer0: thread = one k-pair row (128 rows), 64 samples each ----
    auto layer0 = [&](const float* w1row, const float* b1, int cdim) {
        w1s[tid] = w1row[tid]; w1s[tid + 128] = w1row[tid + 128];
        b1s[tid] = b1[tid];    b1s[tid + 128] = b1[tid + 128];
        __syncthreads();
        int r = tid;                         // 0..127
        int k0 = ((r >> 3) << 4) + (r & 7), k1 = k0 + 8;
        float w0 = w1s[k0], bb0 = b1s[k0];
        float w1v = w1s[k1], bb1 = b1s[k1];
#pragma unroll 4
        for (int i = 0; i < 16; i++) {
            uint4 wrds;
            int s = i * 4;
            float x0 = xv[(s + 0) * 2 + cdim], x1 = xv[(s + 1) * 2 + cdim];
            float x2 = xv[(s + 2) * 2 + cdim], x3 = xv[(s + 3) * 2 + cdim];
            wrds.x = h2u(fmaxf(fmaf(x0, w0, bb0), 0.f), fmaxf(fmaf(x0, w1v, bb1), 0.f));
            wrds.y = h2u(fmaxf(fmaf(x1, w0, bb0), 0.f), fmaxf(fmaf(x1, w1v, bb1), 0.f));
            wrds.z = h2u(fmaxf(fmaf(x2, w0, bb0), 0.f), fmaxf(fmaf(x2, w1v, bb1), 0.f));
            wrds.w = h2u(fmaxf(fmaf(x3, w0, bb0), 0.f), fmaxf(fmaf(x3, w1v, bb1), 0.f));
            *(uint4*)&actu[r * STR2 + s] = wrds;
        }
        // no trailing sync: next gemm's first slab-sync covers act visibility
    };

    // ---- one 64x256 @ 256x256 GEMM; warp tile m64(features) x n64(samples) ----
    auto gemm = [&](int gc, const float* biasg, bool fuse,
                    const float* w5col, float b5, bool is_s) {
        float* bias_c = bias2 + (gc & 1) * 256;
        bias_c[tid] = biasg[tid];
        bias_c[tid + 128] = biasg[tid + 128];
        if (fuse) { w5s[tid] = w5col[tid * 2]; w5s[tid + 128] = w5col[(tid + 128) * 2]; }

        float acc[4][8][4];
#pragma unroll
        for (int a = 0; a < 4; a++)
#pragma unroll
            for (int b = 0; b < 8; b++)
#pragma unroll
                for (int q = 0; q < 4; q++) acc[a][b][q] = 0.f;

#pragma unroll 1
        for (int sl = 0; sl < 8; sl++) {
            int q = gc * 8 + sl;
            asm volatile("cp.async.wait_group 2;");   // own slab-q copies done
            __syncthreads();   // slab q visible to all; all readers of q-1 drained
            prefetch(q + 3);   // overwrites buf (q+3)%4 = (q-1)%4, now free
            const __half* wb = (const __half*)(base + OFF_WBUF + (q % NBUF) * SLAB_BYTES);
#pragma unroll
            for (int kc = 0; kc < 2; kc++) {
                uint4 a[4];
#pragma unroll
                for (int mf = 0; mf < 4; mf++)
                    a[mf] = *(const uint4*)(wb + ((kc * 16 + wid * 4 + mf) * 32 + lane) * 8);
                int kg = sl * 2 + kc;
                const uint32_t* p0 = actu + (kg * 8 + v) * STR2 + u;
                uint32_t b0[8], b1[8];
#pragma unroll
                for (int nf = 0; nf < 8; nf++) {
                    b0[nf] = p0[nf * 8];
                    b1[nf] = p0[4 * STR2 + nf * 8];
                }
#pragma unroll
                for (int mf = 0; mf < 4; mf++)
#pragma unroll
                    for (int nf = 0; nf < 8; nf++)
                        mma_f16(acc[mf][nf], a[mf], b0[nf], b1[nf]);
            }
        }
        __syncthreads();                 // all reads of act done before overwrite

        if (!fuse) {
            // bias + relu + fp16 pair store; row = (wid*4+mf)*8+u holds (f0, f0+8)
#pragma unroll
            for (int mf = 0; mf < 4; mf++) {
                int f0 = wid * 64 + mf * 16 + u;
                int row = (wid * 4 + mf) * 8 + u;
                float bx = bias_c[f0], by = bias_c[f0 + 8];
#pragma unroll
                for (int nf = 0; nf < 8; nf++) {
                    int s0 = nf * 8 + v * 2;
                    uint2 wr;
                    wr.x = h2u(fmaxf(acc[mf][nf][0] + bx, 0.f),
                               fmaxf(acc[mf][nf][2] + by, 0.f));
                    wr.y = h2u(fmaxf(acc[mf][nf][1] + bx, 0.f),
                               fmaxf(acc[mf][nf][3] + by, 0.f));
                    *(uint2*)&actu[row * STR2 + s0] = wr;
                }
            }
            // no trailing sync (bias double-buffered; act covered by next slab-sync)
        } else {
            // fused H->1 dot
            float p[8][2];
#pragma unroll
            for (int nf = 0; nf < 8; nf++) { p[nf][0] = 0.f; p[nf][1] = 0.f; }
#pragma unroll
            for (int mf = 0; mf < 4; mf++) {
                int f0 = wid * 64 + mf * 16 + u;
                float bx = bias_c[f0], by = bias_c[f0 + 8];
                float wa = w5s[f0],   wb5 = w5s[f0 + 8];
#pragma unroll
                for (int nf = 0; nf < 8; nf++) {
                    float v0 = fmaxf(acc[mf][nf][0] + bx, 0.f);
                    float v1 = fmaxf(acc[mf][nf][1] + bx, 0.f);
                    float v2 = fmaxf(acc[mf][nf][2] + by, 0.f);
                    float v3 = fmaxf(acc[mf][nf][3] + by, 0.f);
                    p[nf][0] = fmaf(v0, wa, fmaf(v2, wb5, p[nf][0]));
                    p[nf][1] = fmaf(v1, wa, fmaf(v3, wb5, p[nf][1]));
                }
            }
#pragma unroll
            for (int nf = 0; nf < 8; nf++) {
#pragma unroll
                for (int j = 0; j < 2; j++) {
                    float t = p[nf][j];
                    t += __shfl_down_sync(0xffffffffu, t, 16);
                    t += __shfl_down_sync(0xffffffffu, t, 8);
                    t += __shfl_down_sync(0xffffffffu, t, 4);
                    if (lane < 4)
                        pp[wid * 64 + nf * 8 + lane * 2 + j] = t;
                }
            }
            __syncthreads();
            if (tid < MT) {
                float o = pp[tid] + pp[64 + tid] + pp[128 + tid] + pp[192 + tid] + b5;
                if (is_s) sarr[tid] = tanhf(o);
                else      tarr[tid] = o;
            }
        }
    };

    // ---- main flow: 6 coupling layers, reversed ----
    int gc = 0;
    for (int i = 5; i >= 0; i--) {
        int cdim = (i & 1) ? 0 : 1;
        int other = 1 - cdim;

        layer0(sW1 + i * 512 + cdim * 256, sB1 + i * 256, cdim);
        gemm(gc++, sB2 + i * 256, false, 0, 0.f, false);
        gemm(gc++, sB3 + i * 256, false, 0, 0.f, false);
        gemm(gc++, sB4 + i * 256, true, sW5 + i * 512 + other, sB5[i * 2 + other], true);

        layer0(tW1 + i * 512 + cdim * 256, tB1 + i * 256, cdim);
        gemm(gc++, tB2 + i * 256, false, 0, 0.f, false);
        gemm(gc++, tB3 + i * 256, false, 0, 0.f, false);
        gemm(gc++, tB4 + i * 256, true, tW5 + i * 512 + other, tB5[i * 2 + other], false);

        // coupling update (same-tid as sarr/tarr writers; no sync needed)
        if (tid < MT) {
            float sv = sarr[tid], tv = tarr[tid];
            xv[tid * 2 + other] = (xv[tid * 2 + other] - tv) * expf(-sv);
            ldet -= sv;
        }
        __syncthreads();    // xv visible to next layer0 / output
    }

    if (tid < MT) {
        int g = gbase + tid;
        float2 o;
        o.x = 1.f / (1.f + expf(-xv[tid * 2 + 0]));
        o.y = 1.f / (1.f + expf(-xv[tid * 2 + 1]));
        *(float2*)&out[g * 2] = o;
        out[2 * BSZ + g] = ldet;
    }
    asm volatile("cp.async.wait_group 0;");
}

// ---------------------------------------------------------------------------
extern "C" void kernel_launch(void* const* d_in, const int* in_sizes, int n_in,
                              void* d_out, int out_size) {
    const float* X   = (const float*)d_in[0];
    const float* sW1 = (const float*)d_in[1];
    const float* sB1 = (const float*)d_in[2];
    const float* sW2 = (const float*)d_in[3];
    const float* sB2 = (const float*)d_in[4];
    const float* sW3 = (const float*)d_in[5];
    const float* sB3 = (const float*)d_in[6];
    const float* sW4 = (const float*)d_in[7];
    const float* sB4 = (const float*)d_in[8];
    const float* sW5 = (const float*)d_in[9];
    const float* sB5 = (const float*)d_in[10];
    const float* tW1 = (const float*)d_in[11];
    const float* tB1 = (const float*)d_in[12];
    const float* tW2 = (const float*)d_in[13];
    const float* tB2 = (const float*)d_in[14];
    const float* tW3 = (const float*)d_in[15];
    const float* tB3 = (const float*)d_in[16];
    const float* tW4 = (const float*)d_in[17];
    const float* tB4 = (const float*)d_in[18];
    const float* tW5 = (const float*)d_in[19];
    const float* tB5 = (const float*)d_in[20];

    cudaFuncSetAttribute(realnvp_kernel, cudaFuncAttributeMaxDynamicSharedMemorySize,
                         SMEM_DYN);

    prepack_kernel<<<(NMAT * 8192 + 255) / 256, 256>>>(sW2, sW3, sW4, tW2, tW3, tW4);
    realnvp_kernel<<<BSZ / MT, NTHR, SMEM_DYN>>>(
        X, sW1, sB1, sB2, sB3, sB4, sW5, sB5,
        tW1, tB1, tB2, tB3, tB4, tW5, tB5, (float*)d_out);
}